// round 12
// baseline (speedup 1.0000x reference)
#include <cuda_runtime.h>
#include <cuda_bf16.h>
#include <math.h>
#include <stdint.h>

#define DD 256
#define AA 64
#define NROWS 4096   // B*N
#define NCTA 148     // persistent CTAs for attn
#define NBUF 3       // pipeline depth

// ---------------- scratch (device globals; no allocation allowed) ----------
__device__ float g_b2[DD];           // scale * bq @ Wk   (bias for Qk)
__device__ float g_u[DD];            // scale * Wq^T @ bk
__device__ float g_c;                // scale * bq . bk
__device__ float g_Qk[NROWS * DD];   // cc @ W2 + b2
__device__ float g_qb[NROWS];        // cc_row . g_u + g_c
__device__ float g_wsum[NROWS * DD]; // sum_a p[a] * anchor[a,:]
__device__ float g_S[NROWS];         // sum_a p[a]
// pre-split bf16 B matrices, layout [n][k] (K-major rows, 256 per row)
__device__ __nv_bfloat16 g_BT0_hi[DD * DD];  // W2^T hi  (B for Qk GEMM)
__device__ __nv_bfloat16 g_BT0_lo[DD * DD];
__device__ __nv_bfloat16 g_BT1_hi[DD * DD];  // Wv hi    (B for out GEMM)
__device__ __nv_bfloat16 g_BT1_lo[DD * DD];

// ---------------- small helpers ---------------------------------------------
__device__ __forceinline__ uint32_t smem_u32(const void* p) {
    uint32_t a;
    asm("{ .reg .u64 x; cvta.to.shared.u64 x, %1; cvt.u32.u64 %0, x; }"
        : "=r"(a) : "l"(p));
    return a;
}
__device__ __forceinline__ void bsplit(float x, __nv_bfloat16& h, __nv_bfloat16& l) {
    h = __float2bfloat16(x);
    l = __float2bfloat16(x - __bfloat162float(h));
}
__device__ __forceinline__ uint32_t bpack(__nv_bfloat16 a, __nv_bfloat16 b) {
    __nv_bfloat162 v;
    v.x = a;
    v.y = b;
    return *reinterpret_cast<uint32_t*>(&v);
}

// ---------------- mma / ldmatrix wrappers ------------------------------------
__device__ __forceinline__ void ldsm_x4(uint32_t addr, uint32_t& r0, uint32_t& r1,
                                        uint32_t& r2, uint32_t& r3) {
    asm volatile("ldmatrix.sync.aligned.m8n8.x4.shared.b16 {%0,%1,%2,%3}, [%4];"
                 : "=r"(r0), "=r"(r1), "=r"(r2), "=r"(r3) : "r"(addr));
}
__device__ __forceinline__ void mma_bf16(float* d, uint32_t a0, uint32_t a1,
                                         uint32_t a2, uint32_t a3, uint32_t b0,
                                         uint32_t b1) {
    asm volatile(
        "mma.sync.aligned.m16n8k16.row.col.f32.bf16.bf16.f32 "
        "{%0,%1,%2,%3}, {%4,%5,%6,%7}, {%8,%9}, {%0,%1,%2,%3};"
        : "+f"(d[0]), "+f"(d[1]), "+f"(d[2]), "+f"(d[3])
        : "r"(a0), "r"(a1), "r"(a2), "r"(a3), "r"(b0), "r"(b1));
}

// ---------------- prep: W2 tiles -> BT0 hi/lo; vectors; Wv -> BT1 hi/lo ----
__device__ __forceinline__ void mma_tile4(const float (*As)[68], const float (*Bs)[68],
                                          int ty, int tx, float acc[4][4]) {
#pragma unroll
    for (int kk = 0; kk < 16; ++kk) {
        float4 av = *reinterpret_cast<const float4*>(&As[kk][ty * 4]);
        float4 bv = *reinterpret_cast<const float4*>(&Bs[kk][tx * 4]);
        float ar[4] = {av.x, av.y, av.z, av.w};
        float br[4] = {bv.x, bv.y, bv.z, bv.w};
#pragma unroll
        for (int i = 0; i < 4; ++i)
#pragma unroll
            for (int j = 0; j < 4; ++j)
                acc[i][j] = fmaf(ar[i], br[j], acc[i][j]);
    }
}

__global__ __launch_bounds__(256) void prep_all(const float* __restrict__ Wq,
                                                const float* __restrict__ bq,
                                                const float* __restrict__ Wk,
                                                const float* __restrict__ bk,
                                                const float* __restrict__ Wv) {
    const float scale = 0.0625f;  // 1/sqrt(256)
    const int blk = blockIdx.x;
    const int t = threadIdx.x;
    if (blk >= 18) {
        // convert Wv rows -> g_BT1 hi/lo (B[n][k] = Wv[n][k], direct)
        const int base = (blk - 18) * 32768;  // float elements
#pragma unroll 4
        for (int i = 0; i < 32; ++i) {
            int e4 = t + i * 256;
            float4 x = *reinterpret_cast<const float4*>(Wv + base + e4 * 4);
            __nv_bfloat16 h0, h1, h2, h3, l0, l1, l2, l3;
            bsplit(x.x, h0, l0);
            bsplit(x.y, h1, l1);
            bsplit(x.z, h2, l2);
            bsplit(x.w, h3, l3);
            uint2 vh = make_uint2(bpack(h0, h1), bpack(h2, h3));
            uint2 vl = make_uint2(bpack(l0, l1), bpack(l2, l3));
            *reinterpret_cast<uint2*>(&g_BT1_hi[base + e4 * 4]) = vh;
            *reinterpret_cast<uint2*>(&g_BT1_lo[base + e4 * 4]) = vl;
        }
        return;
    }
    if (blk >= 16) {
        if (blk == 16) {
            float s = 0.f;
            for (int k = 0; k < DD; ++k) s = fmaf(Wq[k * DD + t], bk[k], s);
            g_u[t] = scale * s;
            if (t == 0) {
                float c = 0.f;
                for (int k = 0; k < DD; ++k) c = fmaf(bq[k], bk[k], c);
                g_c = scale * c;
            }
        } else {
            float s = 0.f;
            for (int k = 0; k < DD; ++k) s = fmaf(bq[k], Wk[k * DD + t], s);
            g_b2[t] = scale * s;
        }
        return;
    }
    // W2 tile = scale * Wq^T @ Wk; store transposed bf16 hi/lo: BT0[e][d]
    __shared__ float As[16][68];
    __shared__ float Bs[16][68];
    int tx = t % 16, ty = t / 16;
    int d0 = (blk % 4) * 64, e0 = (blk / 4) * 64;
    float acc[4][4] = {};
    for (int k0 = 0; k0 < DD; k0 += 16) {
        float4 a = *reinterpret_cast<const float4*>(Wq + (k0 + ty) * DD + d0 + tx * 4);
        float4 b = *reinterpret_cast<const float4*>(Wk + (k0 + ty) * DD + e0 + tx * 4);
        *reinterpret_cast<float4*>(&As[ty][tx * 4]) = a;
        *reinterpret_cast<float4*>(&Bs[ty][tx * 4]) = b;
        __syncthreads();
        mma_tile4(As, Bs, ty, tx, acc);
        __syncthreads();
    }
#pragma unroll
    for (int i = 0; i < 4; ++i)
#pragma unroll
        for (int j = 0; j < 4; ++j) {
            float v = scale * acc[i][j];
            __nv_bfloat16 h, l;
            bsplit(v, h, l);
            int e = e0 + tx * 4 + j, d = d0 + ty * 4 + i;
            g_BT0_hi[e * DD + d] = h;
            g_BT0_lo[e * DD + d] = l;
        }
}

// ---------------- qb kernel: g_qb[row] = cc_row . g_u + g_c -----------------
__global__ __launch_bounds__(256) void qb_kernel(const float* __restrict__ cc) {
    __shared__ float s_u[DD];
    const int t = threadIdx.x, w = t >> 5, lane = t & 31;
    s_u[t] = g_u[t];
    __syncthreads();
    const int rb = blockIdx.x * 256 + w * 32;
    const float4* u4 = reinterpret_cast<const float4*>(s_u + lane * 8);
    float4 u0 = u4[0], u1 = u4[1];
#pragma unroll 4
    for (int i = 0; i < 32; ++i) {
        int row = rb + i;
        const float4* c4 =
            reinterpret_cast<const float4*>(cc + (size_t)row * DD + lane * 8);
        float4 a0 = c4[0], a1 = c4[1];
        float s = a0.x * u0.x + a0.y * u0.y + a0.z * u0.z + a0.w * u0.w +
                  a1.x * u1.x + a1.y * u1.y + a1.z * u1.z + a1.w * u1.w;
#pragma unroll
        for (int o = 16; o; o >>= 1) s += __shfl_down_sync(0xffffffffu, s, o);
        if (lane == 0) g_qb[row] = s + g_c;
    }
}

// ---------------- HMMA GEMM: C[4096,256] = A @ B^T (+bias) ------------------
// bf16 split-precision: D = Ahi*Bhi + Ahi*Blo + Alo*Bhi (fp32 accum)
// tile M=128, N=64, K=256 fully resident; padded rows (264 bf16 = 528 B).
// BMODE 0: A = cc,     B = BT0 (W2^T), C = g_Qk, bias = g_b2[n]
// BMODE 1: A = g_wsum, B = BT1 (Wv),   C = out,  bias = bv[n] * g_S[m]
#define KPB 528                       // bytes per padded row
#define SM_BIAS 0
#define SM_AH 256
#define SM_AL (SM_AH + 128 * KPB)     // 67840
#define SM_BH (SM_AL + 128 * KPB)     // 135424
#define SM_BL (SM_BH + 64 * KPB)      // 169216
#define MMA_SMEM (SM_BL + 64 * KPB)   // 203008

template <int BMODE>
__global__ __launch_bounds__(256) void mma_gemm(const float* __restrict__ Afp,
                                                const float* __restrict__ biasp,
                                                float* __restrict__ Cp) {
    extern __shared__ char dsm[];
    const float* A = (BMODE == 0) ? Afp : g_wsum;
    const __nv_bfloat16* BHg = (BMODE == 0) ? g_BT0_hi : g_BT1_hi;
    const __nv_bfloat16* BLg = (BMODE == 0) ? g_BT0_lo : g_BT1_lo;
    const float* bias = (BMODE == 0) ? g_b2 : biasp;
    float* C = (BMODE == 0) ? g_Qk : Cp;

    const int t = threadIdx.x;
    const int w = t >> 5, lane = t & 31;
    const int m0 = blockIdx.x * 128, n0 = blockIdx.y * 64;
    const uint32_t sb = smem_u32(dsm);

    // bias -> smem
    if (t < 64) *reinterpret_cast<float*>(dsm + SM_BIAS + t * 4) = bias[n0 + t];

    // stage B hi/lo: 64 rows x 32 k-groups (8 bf16 = 16 B each)
#pragma unroll 2
    for (int u = t; u < 2048; u += 256) {
        int r = u >> 5, kg = u & 31;
        size_t gi = (size_t)(n0 + r) * DD + kg * 8;
        uint4 vh = *reinterpret_cast<const uint4*>(&BHg[gi]);
        uint4 vl = *reinterpret_cast<const uint4*>(&BLg[gi]);
        *reinterpret_cast<uint4*>(dsm + SM_BH + r * KPB + kg * 16) = vh;
        *reinterpret_cast<uint4*>(dsm + SM_BL + r * KPB + kg * 16) = vl;
    }
    // stage A hi/lo: 128 rows x 32 k-groups, fp32 -> bf16 split
#pragma unroll 2
    for (int u = t; u < 4096; u += 256) {
        int r = u >> 5, kg = u & 31;
        const float* ap = A + (size_t)(m0 + r) * DD + kg * 8;
        float4 f0 = *reinterpret_cast<const float4*>(ap);
        float4 f1 = *reinterpret_cast<const float4*>(ap + 4);
        __nv_bfloat16 h0, h1, h2, h3, h4, h5, h6, h7;
        __nv_bfloat16 l0, l1, l2, l3, l4, l5, l6, l7;
        bsplit(f0.x, h0, l0);
        bsplit(f0.y, h1, l1);
        bsplit(f0.z, h2, l2);
        bsplit(f0.w, h3, l3);
        bsplit(f1.x, h4, l4);
        bsplit(f1.y, h5, l5);
        bsplit(f1.z, h6, l6);
        bsplit(f1.w, h7, l7);
        uint4 vh = make_uint4(bpack(h0, h1), bpack(h2, h3), bpack(h4, h5),
                              bpack(h6, h7));
        uint4 vl = make_uint4(bpack(l0, l1), bpack(l2, l3), bpack(l4, l5),
                              bpack(l6, l7));
        *reinterpret_cast<uint4*>(dsm + SM_AH + r * KPB + kg * 16) = vh;
        *reinterpret_cast<uint4*>(dsm + SM_AL + r * KPB + kg * 16) = vl;
    }
    __syncthreads();

    // per-lane ldmatrix base offsets
    // A x4: lanes 0-15 -> rows m=16w+(lane&15) @k0; lanes 16-31 same rows @k+8
    const uint32_t laneA = (16 * w + (lane & 15)) * KPB + (lane >> 4) * 16;
    // B pair x4: matrices (v=2p rows @k0), (@k8), (v=2p+1 rows @k0), (@k8)
    const uint32_t laneB =
        (((lane >> 4) * 8) + (lane & 7)) * KPB + ((lane >> 3) & 1) * 16;

    float d[8][4];
#pragma unroll
    for (int v = 0; v < 8; ++v)
#pragma unroll
        for (int i = 0; i < 4; ++i) d[v][i] = 0.f;

#pragma unroll
    for (int j = 0; j < 16; ++j) {
        const uint32_t koff = j * 32;  // 16 bf16 = 32 B per k-step
        uint32_t ah0, ah1, ah2, ah3, al0, al1, al2, al3;
        ldsm_x4(sb + SM_AH + laneA + koff, ah0, ah1, ah2, ah3);
        ldsm_x4(sb + SM_AL + laneA + koff, al0, al1, al2, al3);
#pragma unroll
        for (int p = 0; p < 4; ++p) {
            const uint32_t prow = p * 16 * KPB;
            uint32_t bh0, bh1, bh2, bh3, bl0, bl1, bl2, bl3;
            ldsm_x4(sb + SM_BH + prow + laneB + koff, bh0, bh1, bh2, bh3);
            ldsm_x4(sb + SM_BL + prow + laneB + koff, bl0, bl1, bl2, bl3);
            // v = 2p : B frag {bh0,bh1} / {bl0,bl1}
            mma_bf16(d[2 * p], ah0, ah1, ah2, ah3, bh0, bh1);
            mma_bf16(d[2 * p], al0, al1, al2, al3, bh0, bh1);
            mma_bf16(d[2 * p], ah0, ah1, ah2, ah3, bl0, bl1);
            // v = 2p+1 : B frag {bh2,bh3} / {bl2,bl3}
            mma_bf16(d[2 * p + 1], ah0, ah1, ah2, ah3, bh2, bh3);
            mma_bf16(d[2 * p + 1], al0, al1, al2, al3, bh2, bh3);
            mma_bf16(d[2 * p + 1], ah0, ah1, ah2, ah3, bl2, bl3);
        }
    }

    // epilogue: thread holds D rows m=16w+(lane>>2) and +8, cols 2*(lane&3)+8v
    const float* s_bias = reinterpret_cast<const float*>(dsm + SM_BIAS);
    const int gm = m0 + 16 * w + (lane >> 2);
    const int cn = 2 * (lane & 3);
    float sv0 = 1.f, sv1 = 1.f;
    if (BMODE == 1) {
        sv0 = g_S[gm];
        sv1 = g_S[gm + 8];
    }
#pragma unroll
    for (int v = 0; v < 8; ++v) {
        const int n = 8 * v + cn;
        const float b0 = s_bias[n], b1 = s_bias[n + 1];
        float2 o0 = make_float2(d[v][0] + b0 * sv0, d[v][1] + b1 * sv0);
        float2 o1 = make_float2(d[v][2] + b0 * sv1, d[v][3] + b1 * sv1);
        *reinterpret_cast<float2*>(C + (size_t)gm * DD + n0 + n) = o0;
        *reinterpret_cast<float2*>(C + (size_t)(gm + 8) * DD + n0 + n) = o1;
    }
}

// ---------------- attn v7: two independent 256-thread halves per CTA --------
__global__ __launch_bounds__(512) void attn_v7(const float* __restrict__ anchor,
                                               const float* __restrict__ sims) {
    extern __shared__ float sm[];
    float* sP = sm + NBUF * AA * DD;  // [2 halves][8 warps][256]
    __shared__ float s_adj[2][AA];
    __shared__ __align__(8) unsigned long long mbar[NBUF];

    const int t = threadIdx.x;
    const int half = t >> 8;
    const int th = t & 255;
    const int w = th >> 5;
    const int lane = t & 31;
    const int cta = blockIdx.x;
    const int iters = (NROWS - cta + NCTA - 1) / NCTA;

    uint32_t mb_base, sA_base;
    asm("{ .reg .u64 x; cvta.to.shared.u64 x, %1; cvt.u32.u64 %0, x; }"
        : "=r"(mb_base) : "l"(mbar));
    asm("{ .reg .u64 x; cvta.to.shared.u64 x, %1; cvt.u32.u64 %0, x; }"
        : "=r"(sA_base) : "l"(sm));

    if (t == 0) {
#pragma unroll
        for (int j = 0; j < NBUF; ++j)
            asm volatile("mbarrier.init.shared::cta.b64 [%0], 1;"
                         :: "r"(mb_base + j * 8));
    }
    __syncthreads();
    if (t == 0) {
#pragma unroll
        for (int j = 0; j < NBUF; ++j)
            if (j < iters) {
                uint32_t mb = mb_base + j * 8;
                asm volatile("mbarrier.arrive.expect_tx.shared::cta.b64 _, [%0], %1;"
                             :: "r"(mb), "r"(65536));
                asm volatile(
                    "cp.async.bulk.shared::cta.global.mbarrier::complete_tx::bytes "
                    "[%0], [%1], %2, [%3];"
                    :: "r"(sA_base + j * 65536),
                       "l"(anchor + (size_t)(cta + j * NCTA) * AA * DD),
                       "r"(65536), "r"(mb) : "memory");
            }
    }
    __syncthreads();

    const int bar_id = 1 + half;

    for (int it = half; it < iters; it += 2) {
        const int row = cta + it * NCTA;
        const int b = it % NBUF;
        const float* sA = sm + b * AA * DD;

        const float4* qg = reinterpret_cast<const float4*>(g_Qk + (size_t)row * DD);
        float4 q0 = qg[lane], q1 = qg[lane + 32];
        float qb = g_qb[row];
        float simv = (lane < 8) ? sims[row * AA + w + 8 * lane] : 0.f;

        {
            uint32_t mb = mb_base + b * 8;
            int par = (it / NBUF) & 1;
            asm volatile(
                "{ .reg .pred P;\n"
                "WL%=: mbarrier.try_wait.parity.acquire.cta.shared::cta.b64 P, [%0], %1;\n"
                "@!P bra WL%=; }"
                :: "r"(mb), "r"(par) : "memory");
        }

        float4 x0[8], x1[8];
        float val = 0.f;
#pragma unroll
        for (int j = 0; j < 8; ++j) {
            const int a = w + 8 * j;
            const float4* a4 = reinterpret_cast<const float4*>(sA + a * DD);
            x0[j] = a4[lane];
            x1[j] = a4[lane + 32];
            float s = q0.x * x0[j].x + q0.y * x0[j].y + q0.z * x0[j].z +
                      q0.w * x0[j].w + q1.x * x1[j].x + q1.y * x1[j].y +
                      q1.z * x1[j].z + q1.w * x1[j].w;
#pragma unroll
            for (int o = 16; o; o >>= 1) s += __shfl_xor_sync(0xffffffffu, s, o);
            if (lane == j) val = s + qb + simv;
        }
        if (lane < 8) s_adj[half][w + 8 * lane] = val;

        asm volatile("bar.sync %0, 256;" :: "r"(bar_id) : "memory");

        if (th == 0 && it + NBUF < iters) {
            uint32_t mb = mb_base + b * 8;
            asm volatile("mbarrier.arrive.expect_tx.shared::cta.b64 _, [%0], %1;"
                         :: "r"(mb), "r"(65536));
            asm volatile(
                "cp.async.bulk.shared::cta.global.mbarrier::complete_tx::bytes "
                "[%0], [%1], %2, [%3];"
                :: "r"(sA_base + b * 65536),
                   "l"(anchor + (size_t)(row + NBUF * NCTA) * AA * DD),
                   "r"(65536), "r"(mb) : "memory");
        }

        float p0, p1;
        {
            float v0 = s_adj[half][lane], v1 = s_adj[half][lane + 32];
            float sum = v0 + v1;
            float mx = fmaxf(v0, v1);
#pragma unroll
            for (int o = 16; o; o >>= 1) {
                sum += __shfl_xor_sync(0xffffffffu, sum, o);
                mx = fmaxf(mx, __shfl_xor_sync(0xffffffffu, mx, o));
            }
            if (sum != 0.0f) {
                float e0 = __expf(v0 - mx), e1 = __expf(v1 - mx);
                float es = e0 + e1;
#pragma unroll
                for (int o = 16; o; o >>= 1) es += __shfl_xor_sync(0xffffffffu, es, o);
                float inv = 1.0f / es;
                p0 = e0 * inv;
                p1 = e1 * inv;
                if (th == 0) g_S[row] = 1.0f;
            } else {
                p0 = v0;
                p1 = v1;
                if (th == 0) g_S[row] = 0.0f;
            }
        }
        float pa[8];
#pragma unroll
        for (int j = 0; j < 4; ++j)
            pa[j] = __shfl_sync(0xffffffffu, p0, w + 8 * j);
#pragma unroll
        for (int j = 4; j < 8; ++j)
            pa[j] = __shfl_sync(0xffffffffu, p1, w + 8 * j - 32);

        float4 acc0 = make_float4(0.f, 0.f, 0.f, 0.f);
        float4 acc1 = make_float4(0.f, 0.f, 0.f, 0.f);
#pragma unroll
        for (int j = 0; j < 8; ++j) {
            acc0.x = fmaf(pa[j], x0[j].x, acc0.x);
            acc0.y = fmaf(pa[j], x0[j].y, acc0.y);
            acc0.z = fmaf(pa[j], x0[j].z, acc0.z);
            acc0.w = fmaf(pa[j], x0[j].w, acc0.w);
            acc1.x = fmaf(pa[j], x1[j].x, acc1.x);
            acc1.y = fmaf(pa[j], x1[j].y, acc1.y);
            acc1.z = fmaf(pa[j], x1[j].z, acc1.z);
            acc1.w = fmaf(pa[j], x1[j].w, acc1.w);
        }
        float* myP = sP + (half * 8 + w) * DD;
        *reinterpret_cast<float4*>(myP + lane * 4) = acc0;
        *reinterpret_cast<float4*>(myP + 128 + lane * 4) = acc1;

        asm volatile("bar.sync %0, 256;" :: "r"(bar_id) : "memory");

        {
            const float* hp = sP + half * 8 * DD;
            float a = 0.f;
#pragma unroll
            for (int i = 0; i < 8; ++i) a += hp[i * DD + th];
            g_wsum[(size_t)row * DD + th] = a;
        }
    }
}

// ---------------- launch ----------------------------------------------------
extern "C" void kernel_launch(void* const* d_in, const int* in_sizes, int n_in,
                              void* d_out, int out_size) {
    const float* cc     = (const float*)d_in[0];
    const float* anchor = (const float*)d_in[1];
    const float* sims   = (const float*)d_in[2];
    const float* Wq     = (const float*)d_in[3];
    const float* bq     = (const float*)d_in[4];
    const float* Wk     = (const float*)d_in[5];
    const float* bk     = (const float*)d_in[6];
    const float* Wv     = (const float*)d_in[7];
    const float* bv     = (const float*)d_in[8];
    float* out = (float*)d_out;

    const int smem_attn = (NBUF * AA * DD + 16 * DD) * (int)sizeof(float);  // 208 KB
    cudaFuncSetAttribute(attn_v7, cudaFuncAttributeMaxDynamicSharedMemorySize,
                         smem_attn);
    cudaFuncSetAttribute(mma_gemm<0>, cudaFuncAttributeMaxDynamicSharedMemorySize,
                         MMA_SMEM);
    cudaFuncSetAttribute(mma_gemm<1>, cudaFuncAttributeMaxDynamicSharedMemorySize,
                         MMA_SMEM);

    prep_all<<<20, 256>>>(Wq, bq, Wk, bk, Wv);
    qb_kernel<<<16, 256>>>(cc);
    mma_gemm<0><<<dim3(32, 4), 256, MMA_SMEM>>>(cc, nullptr, nullptr);
    attn_v7<<<NCTA, 512, smem_attn>>>(anchor, sims);
    mma_gemm<1><<<dim3(32, 4), 256, MMA_SMEM>>>(nullptr, bv, out);
}

// round 13
// speedup vs baseline: 1.0014x; 1.0014x over previous
#include <cuda_runtime.h>
#include <cuda_bf16.h>
#include <math.h>
#include <stdint.h>

#define DD 256
#define AA 64
#define NROWS 4096   // B*N
#define NCTA 148     // persistent CTAs for attn
#define NBUF 3       // pipeline depth

// ---------------- scratch (device globals; no allocation allowed) ----------
__device__ float g_b2[DD];           // scale * bq @ Wk   (bias for Qk)
__device__ float g_u[DD];            // scale * Wq^T @ bk
__device__ float g_c;                // scale * bq . bk
__device__ float g_Qk[NROWS * DD];   // cc @ W2 + b2
__device__ float g_qb[NROWS];        // cc_row . g_u + g_c
__device__ float g_wsum[NROWS * DD]; // sum_a p[a] * anchor[a,:]
__device__ float g_S[NROWS];         // sum_a p[a]
// pre-split bf16 B matrices, layout [n][k] (K-major rows, 256 per row)
__device__ __nv_bfloat16 g_BT0_hi[DD * DD];  // W2^T hi  (B for Qk GEMM)
__device__ __nv_bfloat16 g_BT0_lo[DD * DD];
__device__ __nv_bfloat16 g_BT1_hi[DD * DD];  // Wv hi    (B for out GEMM)
__device__ __nv_bfloat16 g_BT1_lo[DD * DD];

// ---------------- small helpers ---------------------------------------------
__device__ __forceinline__ uint32_t smem_u32(const void* p) {
    uint32_t a;
    asm("{ .reg .u64 x; cvta.to.shared.u64 x, %1; cvt.u32.u64 %0, x; }"
        : "=r"(a) : "l"(p));
    return a;
}
__device__ __forceinline__ void bsplit(float x, __nv_bfloat16& h, __nv_bfloat16& l) {
    h = __float2bfloat16(x);
    l = __float2bfloat16(x - __bfloat162float(h));
}
__device__ __forceinline__ uint32_t bpack(__nv_bfloat16 a, __nv_bfloat16 b) {
    __nv_bfloat162 v;
    v.x = a;
    v.y = b;
    return *reinterpret_cast<uint32_t*>(&v);
}

// ---------------- mma / ldmatrix wrappers ------------------------------------
__device__ __forceinline__ void ldsm_x4(uint32_t addr, uint32_t& r0, uint32_t& r1,
                                        uint32_t& r2, uint32_t& r3) {
    asm volatile("ldmatrix.sync.aligned.m8n8.x4.shared.b16 {%0,%1,%2,%3}, [%4];"
                 : "=r"(r0), "=r"(r1), "=r"(r2), "=r"(r3) : "r"(addr));
}
__device__ __forceinline__ void mma_bf16(float* d, uint32_t a0, uint32_t a1,
                                         uint32_t a2, uint32_t a3, uint32_t b0,
                                         uint32_t b1) {
    asm volatile(
        "mma.sync.aligned.m16n8k16.row.col.f32.bf16.bf16.f32 "
        "{%0,%1,%2,%3}, {%4,%5,%6,%7}, {%8,%9}, {%0,%1,%2,%3};"
        : "+f"(d[0]), "+f"(d[1]), "+f"(d[2]), "+f"(d[3])
        : "r"(a0), "r"(a1), "r"(a2), "r"(a3), "r"(b0), "r"(b1));
}

// ---------------- prep: W2 tiles -> BT0 hi/lo; vectors; Wv -> BT1 hi/lo ----
__device__ __forceinline__ void mma_tile4(const float (*As)[68], const float (*Bs)[68],
                                          int ty, int tx, float acc[4][4]) {
#pragma unroll
    for (int kk = 0; kk < 16; ++kk) {
        float4 av = *reinterpret_cast<const float4*>(&As[kk][ty * 4]);
        float4 bv = *reinterpret_cast<const float4*>(&Bs[kk][tx * 4]);
        float ar[4] = {av.x, av.y, av.z, av.w};
        float br[4] = {bv.x, bv.y, bv.z, bv.w};
#pragma unroll
        for (int i = 0; i < 4; ++i)
#pragma unroll
            for (int j = 0; j < 4; ++j)
                acc[i][j] = fmaf(ar[i], br[j], acc[i][j]);
    }
}

__global__ __launch_bounds__(256) void prep_all(const float* __restrict__ Wq,
                                                const float* __restrict__ bq,
                                                const float* __restrict__ Wk,
                                                const float* __restrict__ bk,
                                                const float* __restrict__ Wv) {
    const float scale = 0.0625f;  // 1/sqrt(256)
    const int blk = blockIdx.x;
    const int t = threadIdx.x;
    if (blk >= 18) {
        // convert Wv rows -> g_BT1 hi/lo (B[n][k] = Wv[n][k], direct)
        const int base = (blk - 18) * 32768;  // float elements
#pragma unroll 4
        for (int i = 0; i < 32; ++i) {
            int e4 = t + i * 256;
            float4 x = *reinterpret_cast<const float4*>(Wv + base + e4 * 4);
            __nv_bfloat16 h0, h1, h2, h3, l0, l1, l2, l3;
            bsplit(x.x, h0, l0);
            bsplit(x.y, h1, l1);
            bsplit(x.z, h2, l2);
            bsplit(x.w, h3, l3);
            uint2 vh = make_uint2(bpack(h0, h1), bpack(h2, h3));
            uint2 vl = make_uint2(bpack(l0, l1), bpack(l2, l3));
            *reinterpret_cast<uint2*>(&g_BT1_hi[base + e4 * 4]) = vh;
            *reinterpret_cast<uint2*>(&g_BT1_lo[base + e4 * 4]) = vl;
        }
        return;
    }
    if (blk >= 16) {
        if (blk == 16) {
            float s = 0.f;
            for (int k = 0; k < DD; ++k) s = fmaf(Wq[k * DD + t], bk[k], s);
            g_u[t] = scale * s;
            if (t == 0) {
                float c = 0.f;
                for (int k = 0; k < DD; ++k) c = fmaf(bq[k], bk[k], c);
                g_c = scale * c;
            }
        } else {
            float s = 0.f;
            for (int k = 0; k < DD; ++k) s = fmaf(bq[k], Wk[k * DD + t], s);
            g_b2[t] = scale * s;
        }
        return;
    }
    // W2 tile = scale * Wq^T @ Wk; store transposed bf16 hi/lo: BT0[e][d]
    __shared__ float As[16][68];
    __shared__ float Bs[16][68];
    int tx = t % 16, ty = t / 16;
    int d0 = (blk % 4) * 64, e0 = (blk / 4) * 64;
    float acc[4][4] = {};
    for (int k0 = 0; k0 < DD; k0 += 16) {
        float4 a = *reinterpret_cast<const float4*>(Wq + (k0 + ty) * DD + d0 + tx * 4);
        float4 b = *reinterpret_cast<const float4*>(Wk + (k0 + ty) * DD + e0 + tx * 4);
        *reinterpret_cast<float4*>(&As[ty][tx * 4]) = a;
        *reinterpret_cast<float4*>(&Bs[ty][tx * 4]) = b;
        __syncthreads();
        mma_tile4(As, Bs, ty, tx, acc);
        __syncthreads();
    }
#pragma unroll
    for (int i = 0; i < 4; ++i)
#pragma unroll
        for (int j = 0; j < 4; ++j) {
            float v = scale * acc[i][j];
            __nv_bfloat16 h, l;
            bsplit(v, h, l);
            int e = e0 + tx * 4 + j, d = d0 + ty * 4 + i;
            g_BT0_hi[e * DD + d] = h;
            g_BT0_lo[e * DD + d] = l;
        }
}

// ---------------- HMMA GEMM v2: 512 thr, k-split warp sets ------------------
// C[4096,256] = A @ B^T (+bias); bf16 split: D = Ahi*Bhi + Ahi*Blo + Alo*Bhi
// tile M=128, N=64, K=256 resident; padded rows (264 bf16 = 528 B).
// Warps 0-7: k-steps 0-7; warps 8-15: k-steps 8-15; smem reduction of D.
// BMODE 0: A = cc,     B = BT0 (W2^T), C = g_Qk, bias = g_b2[n]; also g_qb
// BMODE 1: A = g_wsum, B = BT1 (Wv),   C = out,  bias = bv[n] * g_S[m]
#define KPB 528                       // bytes per padded row
#define SM_BIAS 0
#define SM_AH 256
#define SM_AL (SM_AH + 128 * KPB)     // 67840
#define SM_BH (SM_AL + 128 * KPB)     // 135424
#define SM_BL (SM_BH + 64 * KPB)      // 169216
#define MMA_SMEM (SM_BL + 64 * KPB)   // 203008
#define SM_RED SM_AH                  // 32 KB partial-D region (A dead by then)

template <int BMODE>
__global__ __launch_bounds__(512) void mma_gemm(const float* __restrict__ Afp,
                                                const float* __restrict__ biasp,
                                                float* __restrict__ Cp) {
    extern __shared__ char dsm[];
    __shared__ float s_qb[128];
    __shared__ float s_u[DD];

    const float* A = (BMODE == 0) ? Afp : g_wsum;
    const __nv_bfloat16* BHg = (BMODE == 0) ? g_BT0_hi : g_BT1_hi;
    const __nv_bfloat16* BLg = (BMODE == 0) ? g_BT0_lo : g_BT1_lo;
    const float* bias = (BMODE == 0) ? g_b2 : biasp;
    float* C = (BMODE == 0) ? g_Qk : Cp;

    const int t = threadIdx.x;
    const int w = t >> 5, lane = t & 31;
    const int wset = w >> 3, wp = w & 7;
    const int m0 = blockIdx.x * 128, n0 = blockIdx.y * 64;
    const uint32_t sb = smem_u32(dsm);
    const bool qb_active = (BMODE == 0) && (blockIdx.y == 0);

    // bias / qb init
    if (t < 64) *reinterpret_cast<float*>(dsm + SM_BIAS + t * 4) = bias[n0 + t];
    if (qb_active) {
        if (t < DD) s_u[t] = g_u[t];
        if (t < 128) s_qb[t] = 0.f;
    }
    __syncthreads();

    // stage B hi/lo: 64 rows x 32 k-groups (8 bf16 = 16 B each)
    for (int u = t; u < 2048; u += 512) {
        int r = u >> 5, kg = u & 31;
        size_t gi = (size_t)(n0 + r) * DD + kg * 8;
        uint4 vh = *reinterpret_cast<const uint4*>(&BHg[gi]);
        uint4 vl = *reinterpret_cast<const uint4*>(&BLg[gi]);
        *reinterpret_cast<uint4*>(dsm + SM_BH + r * KPB + kg * 16) = vh;
        *reinterpret_cast<uint4*>(dsm + SM_BL + r * KPB + kg * 16) = vl;
    }
    // stage A hi/lo: 128 rows x 32 k-groups, fp32 -> bf16 split (+qb partials)
    for (int u = t; u < 4096; u += 512) {
        int r = u >> 5, kg = u & 31;
        const float* ap = A + (size_t)(m0 + r) * DD + kg * 8;
        float4 f0 = *reinterpret_cast<const float4*>(ap);
        float4 f1 = *reinterpret_cast<const float4*>(ap + 4);
        if (qb_active) {
            const float* uu = s_u + kg * 8;
            float p = f0.x * uu[0] + f0.y * uu[1] + f0.z * uu[2] + f0.w * uu[3] +
                      f1.x * uu[4] + f1.y * uu[5] + f1.z * uu[6] + f1.w * uu[7];
            atomicAdd(&s_qb[r], p);
        }
        __nv_bfloat16 h0, h1, h2, h3, h4, h5, h6, h7;
        __nv_bfloat16 l0, l1, l2, l3, l4, l5, l6, l7;
        bsplit(f0.x, h0, l0);
        bsplit(f0.y, h1, l1);
        bsplit(f0.z, h2, l2);
        bsplit(f0.w, h3, l3);
        bsplit(f1.x, h4, l4);
        bsplit(f1.y, h5, l5);
        bsplit(f1.z, h6, l6);
        bsplit(f1.w, h7, l7);
        uint4 vh = make_uint4(bpack(h0, h1), bpack(h2, h3), bpack(h4, h5),
                              bpack(h6, h7));
        uint4 vl = make_uint4(bpack(l0, l1), bpack(l2, l3), bpack(l4, l5),
                              bpack(l6, l7));
        *reinterpret_cast<uint4*>(dsm + SM_AH + r * KPB + kg * 16) = vh;
        *reinterpret_cast<uint4*>(dsm + SM_AL + r * KPB + kg * 16) = vl;
    }
    __syncthreads();

    if (qb_active && t < 128) g_qb[m0 + t] = s_qb[t] + g_c;

    // per-lane ldmatrix base offsets (warp position = wp)
    const uint32_t laneA = (16 * wp + (lane & 15)) * KPB + (lane >> 4) * 16;
    const uint32_t laneB =
        (((lane >> 4) * 8) + (lane & 7)) * KPB + ((lane >> 3) & 1) * 16;

    float d[8][4];
#pragma unroll
    for (int v = 0; v < 8; ++v)
#pragma unroll
        for (int i = 0; i < 4; ++i) d[v][i] = 0.f;

    const int j0 = wset * 8;
#pragma unroll
    for (int jj = 0; jj < 8; ++jj) {
        const uint32_t koff = (uint32_t)(j0 + jj) * 32;  // 16 bf16 = 32 B/step
        uint32_t ah0, ah1, ah2, ah3, al0, al1, al2, al3;
        ldsm_x4(sb + SM_AH + laneA + koff, ah0, ah1, ah2, ah3);
        ldsm_x4(sb + SM_AL + laneA + koff, al0, al1, al2, al3);
#pragma unroll
        for (int p = 0; p < 4; ++p) {
            const uint32_t prow = p * 16 * KPB;
            uint32_t bh0, bh1, bh2, bh3, bl0, bl1, bl2, bl3;
            ldsm_x4(sb + SM_BH + prow + laneB + koff, bh0, bh1, bh2, bh3);
            ldsm_x4(sb + SM_BL + prow + laneB + koff, bl0, bl1, bl2, bl3);
            mma_bf16(d[2 * p], ah0, ah1, ah2, ah3, bh0, bh1);
            mma_bf16(d[2 * p], al0, al1, al2, al3, bh0, bh1);
            mma_bf16(d[2 * p], ah0, ah1, ah2, ah3, bl0, bl1);
            mma_bf16(d[2 * p + 1], ah0, ah1, ah2, ah3, bh2, bh3);
            mma_bf16(d[2 * p + 1], al0, al1, al2, al3, bh2, bh3);
            mma_bf16(d[2 * p + 1], ah0, ah1, ah2, ah3, bl2, bl3);
        }
    }
    __syncthreads();  // A region now dead; safe to reuse as reduction buffer

    // set 1 stores partial D (8 float4 per thread = 128 B/thread, 32 KB total)
    if (wset == 1) {
        float4* red = reinterpret_cast<float4*>(dsm + SM_RED) +
                      (size_t)(wp * 32 + lane) * 8;
#pragma unroll
        for (int v = 0; v < 8; ++v)
            red[v] = make_float4(d[v][0], d[v][1], d[v][2], d[v][3]);
    }
    __syncthreads();

    // set 0 adds partials and writes C
    if (wset == 0) {
        const float4* red = reinterpret_cast<const float4*>(dsm + SM_RED) +
                            (size_t)(wp * 32 + lane) * 8;
        const float* s_bias = reinterpret_cast<const float*>(dsm + SM_BIAS);
        const int gm = m0 + 16 * wp + (lane >> 2);
        const int cn = 2 * (lane & 3);
        float sv0 = 1.f, sv1 = 1.f;
        if (BMODE == 1) {
            sv0 = g_S[gm];
            sv1 = g_S[gm + 8];
        }
#pragma unroll
        for (int v = 0; v < 8; ++v) {
            float4 r = red[v];
            const int n = 8 * v + cn;
            const float b0 = s_bias[n], b1 = s_bias[n + 1];
            float2 o0 = make_float2(d[v][0] + r.x + b0 * sv0,
                                    d[v][1] + r.y + b1 * sv0);
            float2 o1 = make_float2(d[v][2] + r.z + b0 * sv1,
                                    d[v][3] + r.w + b1 * sv1);
            *reinterpret_cast<float2*>(C + (size_t)gm * DD + n0 + n) = o0;
            *reinterpret_cast<float2*>(C + (size_t)(gm + 8) * DD + n0 + n) = o1;
        }
    }
}

// ---------------- attn v7: two independent 256-thread halves per CTA --------
__global__ __launch_bounds__(512) void attn_v7(const float* __restrict__ anchor,
                                               const float* __restrict__ sims) {
    extern __shared__ float sm[];
    float* sP = sm + NBUF * AA * DD;  // [2 halves][8 warps][256]
    __shared__ float s_adj[2][AA];
    __shared__ __align__(8) unsigned long long mbar[NBUF];

    const int t = threadIdx.x;
    const int half = t >> 8;
    const int th = t & 255;
    const int w = th >> 5;
    const int lane = t & 31;
    const int cta = blockIdx.x;
    const int iters = (NROWS - cta + NCTA - 1) / NCTA;

    uint32_t mb_base, sA_base;
    asm("{ .reg .u64 x; cvta.to.shared.u64 x, %1; cvt.u32.u64 %0, x; }"
        : "=r"(mb_base) : "l"(mbar));
    asm("{ .reg .u64 x; cvta.to.shared.u64 x, %1; cvt.u32.u64 %0, x; }"
        : "=r"(sA_base) : "l"(sm));

    if (t == 0) {
#pragma unroll
        for (int j = 0; j < NBUF; ++j)
            asm volatile("mbarrier.init.shared::cta.b64 [%0], 1;"
                         :: "r"(mb_base + j * 8));
    }
    __syncthreads();
    if (t == 0) {
#pragma unroll
        for (int j = 0; j < NBUF; ++j)
            if (j < iters) {
                uint32_t mb = mb_base + j * 8;
                asm volatile("mbarrier.arrive.expect_tx.shared::cta.b64 _, [%0], %1;"
                             :: "r"(mb), "r"(65536));
                asm volatile(
                    "cp.async.bulk.shared::cta.global.mbarrier::complete_tx::bytes "
                    "[%0], [%1], %2, [%3];"
                    :: "r"(sA_base + j * 65536),
                       "l"(anchor + (size_t)(cta + j * NCTA) * AA * DD),
                       "r"(65536), "r"(mb) : "memory");
            }
    }
    __syncthreads();

    const int bar_id = 1 + half;

    for (int it = half; it < iters; it += 2) {
        const int row = cta + it * NCTA;
        const int b = it % NBUF;
        const float* sA = sm + b * AA * DD;

        const float4* qg = reinterpret_cast<const float4*>(g_Qk + (size_t)row * DD);
        float4 q0 = qg[lane], q1 = qg[lane + 32];
        float qb = g_qb[row];
        float simv = (lane < 8) ? sims[row * AA + w + 8 * lane] : 0.f;

        {
            uint32_t mb = mb_base + b * 8;
            int par = (it / NBUF) & 1;
            asm volatile(
                "{ .reg .pred P;\n"
                "WL%=: mbarrier.try_wait.parity.acquire.cta.shared::cta.b64 P, [%0], %1;\n"
                "@!P bra WL%=; }"
                :: "r"(mb), "r"(par) : "memory");
        }

        float4 x0[8], x1[8];
        float val = 0.f;
#pragma unroll
        for (int j = 0; j < 8; ++j) {
            const int a = w + 8 * j;
            const float4* a4 = reinterpret_cast<const float4*>(sA + a * DD);
            x0[j] = a4[lane];
            x1[j] = a4[lane + 32];
            float s = q0.x * x0[j].x + q0.y * x0[j].y + q0.z * x0[j].z +
                      q0.w * x0[j].w + q1.x * x1[j].x + q1.y * x1[j].y +
                      q1.z * x1[j].z + q1.w * x1[j].w;
#pragma unroll
            for (int o = 16; o; o >>= 1) s += __shfl_xor_sync(0xffffffffu, s, o);
            if (lane == j) val = s + qb + simv;
        }
        if (lane < 8) s_adj[half][w + 8 * lane] = val;

        asm volatile("bar.sync %0, 256;" :: "r"(bar_id) : "memory");

        if (th == 0 && it + NBUF < iters) {
            uint32_t mb = mb_base + b * 8;
            asm volatile("mbarrier.arrive.expect_tx.shared::cta.b64 _, [%0], %1;"
                         :: "r"(mb), "r"(65536));
            asm volatile(
                "cp.async.bulk.shared::cta.global.mbarrier::complete_tx::bytes "
                "[%0], [%1], %2, [%3];"
                :: "r"(sA_base + b * 65536),
                   "l"(anchor + (size_t)(row + NBUF * NCTA) * AA * DD),
                   "r"(65536), "r"(mb) : "memory");
        }

        float p0, p1;
        {
            float v0 = s_adj[half][lane], v1 = s_adj[half][lane + 32];
            float sum = v0 + v1;
            float mx = fmaxf(v0, v1);
#pragma unroll
            for (int o = 16; o; o >>= 1) {
                sum += __shfl_xor_sync(0xffffffffu, sum, o);
                mx = fmaxf(mx, __shfl_xor_sync(0xffffffffu, mx, o));
            }
            if (sum != 0.0f) {
                float e0 = __expf(v0 - mx), e1 = __expf(v1 - mx);
                float es = e0 + e1;
#pragma unroll
                for (int o = 16; o; o >>= 1) es += __shfl_xor_sync(0xffffffffu, es, o);
                float inv = 1.0f / es;
                p0 = e0 * inv;
                p1 = e1 * inv;
                if (th == 0) g_S[row] = 1.0f;
            } else {
                p0 = v0;
                p1 = v1;
                if (th == 0) g_S[row] = 0.0f;
            }
        }
        float pa[8];
#pragma unroll
        for (int j = 0; j < 4; ++j)
            pa[j] = __shfl_sync(0xffffffffu, p0, w + 8 * j);
#pragma unroll
        for (int j = 4; j < 8; ++j)
            pa[j] = __shfl_sync(0xffffffffu, p1, w + 8 * j - 32);

        float4 acc0 = make_float4(0.f, 0.f, 0.f, 0.f);
        float4 acc1 = make_float4(0.f, 0.f, 0.f, 0.f);
#pragma unroll
        for (int j = 0; j < 8; ++j) {
            acc0.x = fmaf(pa[j], x0[j].x, acc0.x);
            acc0.y = fmaf(pa[j], x0[j].y, acc0.y);
            acc0.z = fmaf(pa[j], x0[j].z, acc0.z);
            acc0.w = fmaf(pa[j], x0[j].w, acc0.w);
            acc1.x = fmaf(pa[j], x1[j].x, acc1.x);
            acc1.y = fmaf(pa[j], x1[j].y, acc1.y);
            acc1.z = fmaf(pa[j], x1[j].z, acc1.z);
            acc1.w = fmaf(pa[j], x1[j].w, acc1.w);
        }
        float* myP = sP + (half * 8 + w) * DD;
        *reinterpret_cast<float4*>(myP + lane * 4) = acc0;
        *reinterpret_cast<float4*>(myP + 128 + lane * 4) = acc1;

        asm volatile("bar.sync %0, 256;" :: "r"(bar_id) : "memory");

        {
            const float* hp = sP + half * 8 * DD;
            float a = 0.f;
#pragma unroll
            for (int i = 0; i < 8; ++i) a += hp[i * DD + th];
            g_wsum[(size_t)row * DD + th] = a;
        }
    }
}

// ---------------- launch ----------------------------------------------------
extern "C" void kernel_launch(void* const* d_in, const int* in_sizes, int n_in,
                              void* d_out, int out_size) {
    const float* cc     = (const float*)d_in[0];
    const float* anchor = (const float*)d_in[1];
    const float* sims   = (const float*)d_in[2];
    const float* Wq     = (const float*)d_in[3];
    const float* bq     = (const float*)d_in[4];
    const float* Wk     = (const float*)d_in[5];
    const float* bk     = (const float*)d_in[6];
    const float* Wv     = (const float*)d_in[7];
    const float* bv     = (const float*)d_in[8];
    float* out = (float*)d_out;

    const int smem_attn = (NBUF * AA * DD + 16 * DD) * (int)sizeof(float);  // 208 KB
    cudaFuncSetAttribute(attn_v7, cudaFuncAttributeMaxDynamicSharedMemorySize,
                         smem_attn);
    cudaFuncSetAttribute(mma_gemm<0>, cudaFuncAttributeMaxDynamicSharedMemorySize,
                         MMA_SMEM);
    cudaFuncSetAttribute(mma_gemm<1>, cudaFuncAttributeMaxDynamicSharedMemorySize,
                         MMA_SMEM);

    prep_all<<<20, 256>>>(Wq, bq, Wk, bk, Wv);
    mma_gemm<0><<<dim3(32, 4), 512, MMA_SMEM>>>(cc, nullptr, nullptr);
    attn_v7<<<NCTA, 512, smem_attn>>>(anchor, sims);
    mma_gemm<1><<<dim3(32, 4), 512, MMA_SMEM>>>(nullptr, bv, out);
}

// round 14
// speedup vs baseline: 1.0067x; 1.0052x over previous
#include <cuda_runtime.h>
#include <cuda_bf16.h>
#include <math.h>
#include <stdint.h>

#define DD 256
#define AA 64
#define NROWS 4096   // B*N
#define NCTA 148     // persistent CTAs for attn
#define NBUF 3       // pipeline depth
#define KP 264       // padded row length (bf16 elems); 528 B rows
#define KPB 528

// ---------------- scratch (device globals; no allocation allowed) ----------
__device__ float g_b2[DD];           // scale * bq @ Wk   (bias for Qk)
__device__ float g_u[DD];            // scale * Wq^T @ bk
__device__ float g_c;                // scale * bq . bk
__device__ float g_Qk[NROWS * DD];   // cc @ W2 + b2  (fp32, read by attn)
__device__ float g_qb[NROWS];        // cc_row . g_u + g_c
__device__ float g_S[NROWS];         // softmax flag/sum
// pre-split, pre-padded bf16 operands (row stride KP)
__device__ __align__(16) __nv_bfloat16 g_AH0[NROWS * KP];  // cc hi
__device__ __align__(16) __nv_bfloat16 g_AL0[NROWS * KP];  // cc lo
__device__ __align__(16) __nv_bfloat16 g_AH1[NROWS * KP];  // wsum hi
__device__ __align__(16) __nv_bfloat16 g_AL1[NROWS * KP];  // wsum lo
__device__ __align__(16) __nv_bfloat16 g_BH0[DD * KP];     // W2^T hi
__device__ __align__(16) __nv_bfloat16 g_BL0[DD * KP];     // W2^T lo
__device__ __align__(16) __nv_bfloat16 g_BH1[DD * KP];     // Wv hi
__device__ __align__(16) __nv_bfloat16 g_BL1[DD * KP];     // Wv lo

// ---------------- small helpers ---------------------------------------------
__device__ __forceinline__ uint32_t smem_u32(const void* p) {
    uint32_t a;
    asm("{ .reg .u64 x; cvta.to.shared.u64 x, %1; cvt.u32.u64 %0, x; }"
        : "=r"(a) : "l"(p));
    return a;
}
__device__ __forceinline__ void bsplit(float x, __nv_bfloat16& h, __nv_bfloat16& l) {
    h = __float2bfloat16(x);
    l = __float2bfloat16(x - __bfloat162float(h));
}
__device__ __forceinline__ uint32_t bpack(__nv_bfloat16 a, __nv_bfloat16 b) {
    __nv_bfloat162 v;
    v.x = a;
    v.y = b;
    return *reinterpret_cast<uint32_t*>(&v);
}

// ---------------- mma / ldmatrix wrappers ------------------------------------
__device__ __forceinline__ void ldsm_x4(uint32_t addr, uint32_t& r0, uint32_t& r1,
                                        uint32_t& r2, uint32_t& r3) {
    asm volatile("ldmatrix.sync.aligned.m8n8.x4.shared.b16 {%0,%1,%2,%3}, [%4];"
                 : "=r"(r0), "=r"(r1), "=r"(r2), "=r"(r3) : "r"(addr));
}
__device__ __forceinline__ void mma_bf16(float* d, uint32_t a0, uint32_t a1,
                                         uint32_t a2, uint32_t a3, uint32_t b0,
                                         uint32_t b1) {
    asm volatile(
        "mma.sync.aligned.m16n8k16.row.col.f32.bf16.bf16.f32 "
        "{%0,%1,%2,%3}, {%4,%5,%6,%7}, {%8,%9}, {%0,%1,%2,%3};"
        : "+f"(d[0]), "+f"(d[1]), "+f"(d[2]), "+f"(d[3])
        : "r"(a0), "r"(a1), "r"(a2), "r"(a3), "r"(b0), "r"(b1));
}

// ---------------- prep_all: weights -> split/padded; vectors ----------------
__device__ __forceinline__ void mma_tile4(const float (*As)[68], const float (*Bs)[68],
                                          int ty, int tx, float acc[4][4]) {
#pragma unroll
    for (int kk = 0; kk < 16; ++kk) {
        float4 av = *reinterpret_cast<const float4*>(&As[kk][ty * 4]);
        float4 bv = *reinterpret_cast<const float4*>(&Bs[kk][tx * 4]);
        float ar[4] = {av.x, av.y, av.z, av.w};
        float br[4] = {bv.x, bv.y, bv.z, bv.w};
#pragma unroll
        for (int i = 0; i < 4; ++i)
#pragma unroll
            for (int j = 0; j < 4; ++j)
                acc[i][j] = fmaf(ar[i], br[j], acc[i][j]);
    }
}

__global__ __launch_bounds__(256) void prep_all(const float* __restrict__ Wq,
                                                const float* __restrict__ bq,
                                                const float* __restrict__ Wk,
                                                const float* __restrict__ bk,
                                                const float* __restrict__ Wv) {
    const float scale = 0.0625f;  // 1/sqrt(256)
    const int blk = blockIdx.x;
    const int t = threadIdx.x;
    if (blk >= 18) {
        // Wv rows -> g_BH1/g_BL1 (padded layout)
        const int rbase = (blk - 18) * 128;
#pragma unroll
        for (int i = 0; i < 16; ++i) {
            int u = t + i * 256;            // 4096 units = 128 rows x 32 kg
            int r = rbase + (u >> 5), kg = u & 31;
            const float* ap = Wv + (size_t)r * DD + kg * 8;
            float4 f0 = *reinterpret_cast<const float4*>(ap);
            float4 f1 = *reinterpret_cast<const float4*>(ap + 4);
            __nv_bfloat16 h0, h1, h2, h3, h4, h5, h6, h7;
            __nv_bfloat16 l0, l1, l2, l3, l4, l5, l6, l7;
            bsplit(f0.x, h0, l0); bsplit(f0.y, h1, l1);
            bsplit(f0.z, h2, l2); bsplit(f0.w, h3, l3);
            bsplit(f1.x, h4, l4); bsplit(f1.y, h5, l5);
            bsplit(f1.z, h6, l6); bsplit(f1.w, h7, l7);
            uint4 vh = make_uint4(bpack(h0, h1), bpack(h2, h3), bpack(h4, h5),
                                  bpack(h6, h7));
            uint4 vl = make_uint4(bpack(l0, l1), bpack(l2, l3), bpack(l4, l5),
                                  bpack(l6, l7));
            *reinterpret_cast<uint4*>(&g_BH1[(size_t)r * KP + kg * 8]) = vh;
            *reinterpret_cast<uint4*>(&g_BL1[(size_t)r * KP + kg * 8]) = vl;
        }
        return;
    }
    if (blk >= 16) {
        // vector preps with MLP-friendly unrolled multi-accumulator loops
        if (blk == 16) {
            float s0 = 0.f, s1 = 0.f, s2 = 0.f, s3 = 0.f;
#pragma unroll 16
            for (int k = 0; k < DD; k += 4) {
                s0 = fmaf(Wq[(k + 0) * DD + t], bk[k + 0], s0);
                s1 = fmaf(Wq[(k + 1) * DD + t], bk[k + 1], s1);
                s2 = fmaf(Wq[(k + 2) * DD + t], bk[k + 2], s2);
                s3 = fmaf(Wq[(k + 3) * DD + t], bk[k + 3], s3);
            }
            g_u[t] = scale * ((s0 + s1) + (s2 + s3));
            if (t == 0) {
                float c0 = 0.f, c1 = 0.f;
#pragma unroll 16
                for (int k = 0; k < DD; k += 2) {
                    c0 = fmaf(bq[k], bk[k], c0);
                    c1 = fmaf(bq[k + 1], bk[k + 1], c1);
                }
                g_c = scale * (c0 + c1);
            }
        } else {
            float s0 = 0.f, s1 = 0.f, s2 = 0.f, s3 = 0.f;
#pragma unroll 16
            for (int k = 0; k < DD; k += 4) {
                s0 = fmaf(bq[k + 0], Wk[(k + 0) * DD + t], s0);
                s1 = fmaf(bq[k + 1], Wk[(k + 1) * DD + t], s1);
                s2 = fmaf(bq[k + 2], Wk[(k + 2) * DD + t], s2);
                s3 = fmaf(bq[k + 3], Wk[(k + 3) * DD + t], s3);
            }
            g_b2[t] = scale * ((s0 + s1) + (s2 + s3));
        }
        return;
    }
    // W2 tile = scale * Wq^T @ Wk; store transposed split: BT0[e][d]
    __shared__ float As[16][68];
    __shared__ float Bs[16][68];
    int tx = t % 16, ty = t / 16;
    int d0 = (blk % 4) * 64, e0 = (blk / 4) * 64;
    float acc[4][4] = {};
    for (int k0 = 0; k0 < DD; k0 += 16) {
        float4 a = *reinterpret_cast<const float4*>(Wq + (k0 + ty) * DD + d0 + tx * 4);
        float4 b = *reinterpret_cast<const float4*>(Wk + (k0 + ty) * DD + e0 + tx * 4);
        *reinterpret_cast<float4*>(&As[ty][tx * 4]) = a;
        *reinterpret_cast<float4*>(&Bs[ty][tx * 4]) = b;
        __syncthreads();
        mma_tile4(As, Bs, ty, tx, acc);
        __syncthreads();
    }
#pragma unroll
    for (int i = 0; i < 4; ++i)
#pragma unroll
        for (int j = 0; j < 4; ++j) {
            float v = scale * acc[i][j];
            __nv_bfloat16 h, l;
            bsplit(v, h, l);
            int e = e0 + tx * 4 + j, d = d0 + ty * 4 + i;
            g_BH0[(size_t)e * KP + d] = h;
            g_BL0[(size_t)e * KP + d] = l;
        }
}

// ---------------- prep_cc: cc -> split/padded + qb --------------------------
__global__ __launch_bounds__(256) void prep_cc(const float* __restrict__ cc) {
    __shared__ float s_u[DD];
    __shared__ float s_qb[64];
    const int t = threadIdx.x;
    s_u[t] = g_u[t];
    if (t < 64) s_qb[t] = 0.f;
    __syncthreads();
    const int r0 = blockIdx.x * 64;
#pragma unroll
    for (int i = 0; i < 8; ++i) {
        int u = t + i * 256;                 // 2048 units = 64 rows x 32 kg
        int r = u >> 5, kg = u & 31;
        const float* ap = cc + (size_t)(r0 + r) * DD + kg * 8;
        float4 f0 = *reinterpret_cast<const float4*>(ap);
        float4 f1 = *reinterpret_cast<const float4*>(ap + 4);
        const float* uu = s_u + kg * 8;
        float p = f0.x * uu[0] + f0.y * uu[1] + f0.z * uu[2] + f0.w * uu[3] +
                  f1.x * uu[4] + f1.y * uu[5] + f1.z * uu[6] + f1.w * uu[7];
        atomicAdd(&s_qb[r], p);
        __nv_bfloat16 h0, h1, h2, h3, h4, h5, h6, h7;
        __nv_bfloat16 l0, l1, l2, l3, l4, l5, l6, l7;
        bsplit(f0.x, h0, l0); bsplit(f0.y, h1, l1);
        bsplit(f0.z, h2, l2); bsplit(f0.w, h3, l3);
        bsplit(f1.x, h4, l4); bsplit(f1.y, h5, l5);
        bsplit(f1.z, h6, l6); bsplit(f1.w, h7, l7);
        uint4 vh = make_uint4(bpack(h0, h1), bpack(h2, h3), bpack(h4, h5),
                              bpack(h6, h7));
        uint4 vl = make_uint4(bpack(l0, l1), bpack(l2, l3), bpack(l4, l5),
                              bpack(l6, l7));
        size_t gi = (size_t)(r0 + r) * KP + kg * 8;
        *reinterpret_cast<uint4*>(&g_AH0[gi]) = vh;
        *reinterpret_cast<uint4*>(&g_AL0[gi]) = vl;
    }
    __syncthreads();
    if (t < 64) g_qb[r0 + t] = s_qb[t] + g_c;
}

// ---------------- HMMA GEMM v3: DMA-staged, 512 thr, k-split ----------------
// C[4096,256] = A @ B^T (+bias); bf16 split: D = Ahi*Bhi + Ahi*Blo + Alo*Bhi
// All operands pre-split/pre-padded in global; staging = 4 cp.async.bulk.
#define SM_MB   0
#define SM_BIAS 16
#define SM_AH   512
#define SM_AL   (SM_AH + 128 * KPB)   // +67584
#define SM_BH   (SM_AL + 128 * KPB)
#define SM_BL   (SM_BH + 64 * KPB)    // +33792
#define MMA_SMEM (SM_BL + 64 * KPB)   // 203264
#define SM_RED  SM_AH
#define TXTOTAL (2 * 128 * KPB + 2 * 64 * KPB)  // 202752

template <int BMODE>
__global__ __launch_bounds__(512) void mma_gemm(const float* __restrict__ biasp,
                                                float* __restrict__ Cp) {
    extern __shared__ char dsm[];
    const __nv_bfloat16* AHg = (BMODE == 0) ? g_AH0 : g_AH1;
    const __nv_bfloat16* ALg = (BMODE == 0) ? g_AL0 : g_AL1;
    const __nv_bfloat16* BHg = (BMODE == 0) ? g_BH0 : g_BH1;
    const __nv_bfloat16* BLg = (BMODE == 0) ? g_BL0 : g_BL1;
    const float* bias = (BMODE == 0) ? g_b2 : biasp;
    float* C = (BMODE == 0) ? g_Qk : Cp;

    const int t = threadIdx.x;
    const int w = t >> 5, lane = t & 31;
    const int wset = w >> 3, wp = w & 7;
    const int m0 = blockIdx.x * 128, n0 = blockIdx.y * 64;
    const uint32_t sb = smem_u32(dsm);

    if (t == 0)
        asm volatile("mbarrier.init.shared::cta.b64 [%0], 1;" :: "r"(sb + SM_MB)
                     : "memory");
    __syncthreads();
    if (t == 0) {
        asm volatile("mbarrier.arrive.expect_tx.shared::cta.b64 _, [%0], %1;"
                     :: "r"(sb + SM_MB), "r"((uint32_t)TXTOTAL) : "memory");
        asm volatile(
            "cp.async.bulk.shared::cta.global.mbarrier::complete_tx::bytes "
            "[%0], [%1], %2, [%3];"
            :: "r"(sb + SM_AH), "l"(AHg + (size_t)m0 * KP),
               "r"(128 * KPB), "r"(sb + SM_MB) : "memory");
        asm volatile(
            "cp.async.bulk.shared::cta.global.mbarrier::complete_tx::bytes "
            "[%0], [%1], %2, [%3];"
            :: "r"(sb + SM_AL), "l"(ALg + (size_t)m0 * KP),
               "r"(128 * KPB), "r"(sb + SM_MB) : "memory");
        asm volatile(
            "cp.async.bulk.shared::cta.global.mbarrier::complete_tx::bytes "
            "[%0], [%1], %2, [%3];"
            :: "r"(sb + SM_BH), "l"(BHg + (size_t)n0 * KP),
               "r"(64 * KPB), "r"(sb + SM_MB) : "memory");
        asm volatile(
            "cp.async.bulk.shared::cta.global.mbarrier::complete_tx::bytes "
            "[%0], [%1], %2, [%3];"
            :: "r"(sb + SM_BL), "l"(BLg + (size_t)n0 * KP),
               "r"(64 * KPB), "r"(sb + SM_MB) : "memory");
    }
    if (t < 64)
        *reinterpret_cast<float*>(dsm + SM_BIAS + t * 4) = bias[n0 + t];

    // wait for DMA
    asm volatile(
        "{ .reg .pred P;\n"
        "WL%=: mbarrier.try_wait.parity.acquire.cta.shared::cta.b64 P, [%0], 0;\n"
        "@!P bra WL%=; }"
        :: "r"(sb + SM_MB) : "memory");

    // per-lane ldmatrix base offsets (warp position = wp)
    const uint32_t laneA = (16 * wp + (lane & 15)) * KPB + (lane >> 4) * 16;
    const uint32_t laneB =
        (((lane >> 4) * 8) + (lane & 7)) * KPB + ((lane >> 3) & 1) * 16;

    float d[8][4];
#pragma unroll
    for (int v = 0; v < 8; ++v)
#pragma unroll
        for (int i = 0; i < 4; ++i) d[v][i] = 0.f;

    const int j0 = wset * 8;
#pragma unroll
    for (int jj = 0; jj < 8; ++jj) {
        const uint32_t koff = (uint32_t)(j0 + jj) * 32;  // 16 bf16 = 32 B/step
        uint32_t ah0, ah1, ah2, ah3, al0, al1, al2, al3;
        ldsm_x4(sb + SM_AH + laneA + koff, ah0, ah1, ah2, ah3);
        ldsm_x4(sb + SM_AL + laneA + koff, al0, al1, al2, al3);
#pragma unroll
        for (int p = 0; p < 4; ++p) {
            const uint32_t prow = p * 16 * KPB;
            uint32_t bh0, bh1, bh2, bh3, bl0, bl1, bl2, bl3;
            ldsm_x4(sb + SM_BH + prow + laneB + koff, bh0, bh1, bh2, bh3);
            ldsm_x4(sb + SM_BL + prow + laneB + koff, bl0, bl1, bl2, bl3);
            mma_bf16(d[2 * p], ah0, ah1, ah2, ah3, bh0, bh1);
            mma_bf16(d[2 * p], al0, al1, al2, al3, bh0, bh1);
            mma_bf16(d[2 * p], ah0, ah1, ah2, ah3, bl0, bl1);
            mma_bf16(d[2 * p + 1], ah0, ah1, ah2, ah3, bh2, bh3);
            mma_bf16(d[2 * p + 1], al0, al1, al2, al3, bh2, bh3);
            mma_bf16(d[2 * p + 1], ah0, ah1, ah2, ah3, bl2, bl3);
        }
    }
    __syncthreads();  // A region dead; safe to reuse as reduction buffer

    if (wset == 1) {
        float4* red = reinterpret_cast<float4*>(dsm + SM_RED) +
                      (size_t)(wp * 32 + lane) * 8;
#pragma unroll
        for (int v = 0; v < 8; ++v)
            red[v] = make_float4(d[v][0], d[v][1], d[v][2], d[v][3]);
    }
    __syncthreads();

    if (wset == 0) {
        const float4* red = reinterpret_cast<const float4*>(dsm + SM_RED) +
                            (size_t)(wp * 32 + lane) * 8;
        const float* s_bias = reinterpret_cast<const float*>(dsm + SM_BIAS);
        const int gm = m0 + 16 * wp + (lane >> 2);
        const int cn = 2 * (lane & 3);
        float sv0 = 1.f, sv1 = 1.f;
        if (BMODE == 1) {
            sv0 = g_S[gm];
            sv1 = g_S[gm + 8];
        }
#pragma unroll
        for (int v = 0; v < 8; ++v) {
            float4 r = red[v];
            const int n = 8 * v + cn;
            const float b0 = s_bias[n], b1 = s_bias[n + 1];
            float2 o0 = make_float2(d[v][0] + r.x + b0 * sv0,
                                    d[v][1] + r.y + b1 * sv0);
            float2 o1 = make_float2(d[v][2] + r.z + b0 * sv1,
                                    d[v][3] + r.w + b1 * sv1);
            *reinterpret_cast<float2*>(C + (size_t)gm * DD + n0 + n) = o0;
            *reinterpret_cast<float2*>(C + (size_t)(gm + 8) * DD + n0 + n) = o1;
        }
    }
}

// ---------------- attn v7: two independent 256-thread halves per CTA --------
__global__ __launch_bounds__(512) void attn_v7(const float* __restrict__ anchor,
                                               const float* __restrict__ sims) {
    extern __shared__ float sm[];
    float* sP = sm + NBUF * AA * DD;  // [2 halves][8 warps][256]
    __shared__ float s_adj[2][AA];
    __shared__ __align__(8) unsigned long long mbar[NBUF];

    const int t = threadIdx.x;
    const int half = t >> 8;
    const int th = t & 255;
    const int w = th >> 5;
    const int lane = t & 31;
    const int cta = blockIdx.x;
    const int iters = (NROWS - cta + NCTA - 1) / NCTA;

    uint32_t mb_base, sA_base;
    asm("{ .reg .u64 x; cvta.to.shared.u64 x, %1; cvt.u32.u64 %0, x; }"
        : "=r"(mb_base) : "l"(mbar));
    asm("{ .reg .u64 x; cvta.to.shared.u64 x, %1; cvt.u32.u64 %0, x; }"
        : "=r"(sA_base) : "l"(sm));

    if (t == 0) {
#pragma unroll
        for (int j = 0; j < NBUF; ++j)
            asm volatile("mbarrier.init.shared::cta.b64 [%0], 1;"
                         :: "r"(mb_base + j * 8));
    }
    __syncthreads();
    if (t == 0) {
#pragma unroll
        for (int j = 0; j < NBUF; ++j)
            if (j < iters) {
                uint32_t mb = mb_base + j * 8;
                asm volatile("mbarrier.arrive.expect_tx.shared::cta.b64 _, [%0], %1;"
                             :: "r"(mb), "r"(65536));
                asm volatile(
                    "cp.async.bulk.shared::cta.global.mbarrier::complete_tx::bytes "
                    "[%0], [%1], %2, [%3];"
                    :: "r"(sA_base + j * 65536),
                       "l"(anchor + (size_t)(cta + j * NCTA) * AA * DD),
                       "r"(65536), "r"(mb) : "memory");
            }
    }
    __syncthreads();

    const int bar_id = 1 + half;

    for (int it = half; it < iters; it += 2) {
        const int row = cta + it * NCTA;
        const int b = it % NBUF;
        const float* sA = sm + b * AA * DD;

        const float4* qg = reinterpret_cast<const float4*>(g_Qk + (size_t)row * DD);
        float4 q0 = qg[lane], q1 = qg[lane + 32];
        float qb = g_qb[row];
        float simv = (lane < 8) ? sims[row * AA + w + 8 * lane] : 0.f;

        {
            uint32_t mb = mb_base + b * 8;
            int par = (it / NBUF) & 1;
            asm volatile(
                "{ .reg .pred P;\n"
                "WL%=: mbarrier.try_wait.parity.acquire.cta.shared::cta.b64 P, [%0], %1;\n"
                "@!P bra WL%=; }"
                :: "r"(mb), "r"(par) : "memory");
        }

        float4 x0[8], x1[8];
        float val = 0.f;
#pragma unroll
        for (int j = 0; j < 8; ++j) {
            const int a = w + 8 * j;
            const float4* a4 = reinterpret_cast<const float4*>(sA + a * DD);
            x0[j] = a4[lane];
            x1[j] = a4[lane + 32];
            float s = q0.x * x0[j].x + q0.y * x0[j].y + q0.z * x0[j].z +
                      q0.w * x0[j].w + q1.x * x1[j].x + q1.y * x1[j].y +
                      q1.z * x1[j].z + q1.w * x1[j].w;
#pragma unroll
            for (int o = 16; o; o >>= 1) s += __shfl_xor_sync(0xffffffffu, s, o);
            if (lane == j) val = s + qb + simv;
        }
        if (lane < 8) s_adj[half][w + 8 * lane] = val;

        asm volatile("bar.sync %0, 256;" :: "r"(bar_id) : "memory");

        if (th == 0 && it + NBUF < iters) {
            uint32_t mb = mb_base + b * 8;
            asm volatile("mbarrier.arrive.expect_tx.shared::cta.b64 _, [%0], %1;"
                         :: "r"(mb), "r"(65536));
            asm volatile(
                "cp.async.bulk.shared::cta.global.mbarrier::complete_tx::bytes "
                "[%0], [%1], %2, [%3];"
                :: "r"(sA_base + b * 65536),
                   "l"(anchor + (size_t)(row + NBUF * NCTA) * AA * DD),
                   "r"(65536), "r"(mb) : "memory");
        }

        float p0, p1;
        {
            float v0 = s_adj[half][lane], v1 = s_adj[half][lane + 32];
            float sum = v0 + v1;
            float mx = fmaxf(v0, v1);
#pragma unroll
            for (int o = 16; o; o >>= 1) {
                sum += __shfl_xor_sync(0xffffffffu, sum, o);
                mx = fmaxf(mx, __shfl_xor_sync(0xffffffffu, mx, o));
            }
            if (sum != 0.0f) {
                float e0 = __expf(v0 - mx), e1 = __expf(v1 - mx);
                float es = e0 + e1;
#pragma unroll
                for (int o = 16; o; o >>= 1) es += __shfl_xor_sync(0xffffffffu, es, o);
                float inv = 1.0f / es;
                p0 = e0 * inv;
                p1 = e1 * inv;
                if (th == 0) g_S[row] = 1.0f;
            } else {
                p0 = v0;
                p1 = v1;
                if (th == 0) g_S[row] = 0.0f;
            }
        }
        float pa[8];
#pragma unroll
        for (int j = 0; j < 4; ++j)
            pa[j] = __shfl_sync(0xffffffffu, p0, w + 8 * j);
#pragma unroll
        for (int j = 4; j < 8; ++j)
            pa[j] = __shfl_sync(0xffffffffu, p1, w + 8 * j - 32);

        float4 acc0 = make_float4(0.f, 0.f, 0.f, 0.f);
        float4 acc1 = make_float4(0.f, 0.f, 0.f, 0.f);
#pragma unroll
        for (int j = 0; j < 8; ++j) {
            acc0.x = fmaf(pa[j], x0[j].x, acc0.x);
            acc0.y = fmaf(pa[j], x0[j].y, acc0.y);
            acc0.z = fmaf(pa[j], x0[j].z, acc0.z);
            acc0.w = fmaf(pa[j], x0[j].w, acc0.w);
            acc1.x = fmaf(pa[j], x1[j].x, acc1.x);
            acc1.y = fmaf(pa[j], x1[j].y, acc1.y);
            acc1.z = fmaf(pa[j], x1[j].z, acc1.z);
            acc1.w = fmaf(pa[j], x1[j].w, acc1.w);
        }
        float* myP = sP + (half * 8 + w) * DD;
        *reinterpret_cast<float4*>(myP + lane * 4) = acc0;
        *reinterpret_cast<float4*>(myP + 128 + lane * 4) = acc1;

        asm volatile("bar.sync %0, 256;" :: "r"(bar_id) : "memory");

        {
            const float* hp = sP + half * 8 * DD;
            float a = 0.f;
#pragma unroll
            for (int i = 0; i < 8; ++i) a += hp[i * DD + th];
            // write wsum directly as bf16 hi/lo (padded layout for gemm<1> DMA)
            __nv_bfloat16 h, l;
            bsplit(a, h, l);
            size_t gi = (size_t)row * KP + th;
            g_AH1[gi] = h;
            g_AL1[gi] = l;
        }
    }
}

// ---------------- launch ----------------------------------------------------
extern "C" void kernel_launch(void* const* d_in, const int* in_sizes, int n_in,
                              void* d_out, int out_size) {
    const float* cc     = (const float*)d_in[0];
    const float* anchor = (const float*)d_in[1];
    const float* sims   = (const float*)d_in[2];
    const float* Wq     = (const float*)d_in[3];
    const float* bq     = (const float*)d_in[4];
    const float* Wk     = (const float*)d_in[5];
    const float* bk     = (const float*)d_in[6];
    const float* Wv     = (const float*)d_in[7];
    const float* bv     = (const float*)d_in[8];
    float* out = (float*)d_out;

    const int smem_attn = (NBUF * AA * DD + 16 * DD) * (int)sizeof(float);  // 208 KB
    cudaFuncSetAttribute(attn_v7, cudaFuncAttributeMaxDynamicSharedMemorySize,
                         smem_attn);
    cudaFuncSetAttribute(mma_gemm<0>, cudaFuncAttributeMaxDynamicSharedMemorySize,
                         MMA_SMEM);
    cudaFuncSetAttribute(mma_gemm<1>, cudaFuncAttributeMaxDynamicSharedMemorySize,
                         MMA_SMEM);

    prep_all<<<20, 256>>>(Wq, bq, Wk, bk, Wv);
    prep_cc<<<64, 256>>>(cc);
    mma_gemm<0><<<dim3(32, 4), 512, MMA_SMEM>>>(nullptr, nullptr);
    attn_v7<<<NCTA, 512, smem_attn>>>(anchor, sims);
    mma_gemm<1><<<dim3(32, 4), 512, MMA_SMEM>>>(bv, out);
}

// round 15
// speedup vs baseline: 1.2222x; 1.2141x over previous
#include <cuda_runtime.h>
#include <cuda_bf16.h>
#include <math.h>
#include <stdint.h>

#define DD 256
#define AA 64
#define NROWS 4096   // B*N
#define NCTA 148     // persistent CTAs for attn
#define NBUF 3       // pipeline depth
#define KP 264       // padded row length (bf16 elems); 528 B rows
#define KPB 528

// ---------------- scratch (device globals; no allocation allowed) ----------
__device__ float g_b2[DD];           // scale * bq @ Wk   (bias for Qk)
__device__ float g_u[DD];            // scale * Wq^T @ bk
__device__ float g_c;                // scale * bq . bk
__device__ float g_Qk[NROWS * DD];   // cc @ W2 + b2  (fp32, read by attn)
__device__ float g_qb[NROWS];        // cc_row . g_u + g_c
__device__ float g_wsum[NROWS * DD]; // sum_a p[a] * anchor[a,:]
__device__ float g_S[NROWS];         // softmax flag
// pre-split, pre-padded bf16 weight matrices (row stride KP, [n][k])
__device__ __align__(16) __nv_bfloat16 g_BH0[DD * KP];  // W2^T hi
__device__ __align__(16) __nv_bfloat16 g_BL0[DD * KP];  // W2^T lo
__device__ __align__(16) __nv_bfloat16 g_BH1[DD * KP];  // Wv hi
__device__ __align__(16) __nv_bfloat16 g_BL1[DD * KP];  // Wv lo

// ---------------- small helpers ---------------------------------------------
__device__ __forceinline__ uint32_t smem_u32(const void* p) {
    uint32_t a;
    asm("{ .reg .u64 x; cvta.to.shared.u64 x, %1; cvt.u32.u64 %0, x; }"
        : "=r"(a) : "l"(p));
    return a;
}
__device__ __forceinline__ void bsplit(float x, __nv_bfloat16& h, __nv_bfloat16& l) {
    h = __float2bfloat16(x);
    l = __float2bfloat16(x - __bfloat162float(h));
}
__device__ __forceinline__ uint32_t bpack(__nv_bfloat16 a, __nv_bfloat16 b) {
    __nv_bfloat162 v;
    v.x = a;
    v.y = b;
    return *reinterpret_cast<uint32_t*>(&v);
}

// ---------------- mma / ldmatrix wrappers ------------------------------------
__device__ __forceinline__ void ldsm_x4(uint32_t addr, uint32_t& r0, uint32_t& r1,
                                        uint32_t& r2, uint32_t& r3) {
    asm volatile("ldmatrix.sync.aligned.m8n8.x4.shared.b16 {%0,%1,%2,%3}, [%4];"
                 : "=r"(r0), "=r"(r1), "=r"(r2), "=r"(r3) : "r"(addr));
}
__device__ __forceinline__ void mma_bf16(float* d, uint32_t a0, uint32_t a1,
                                         uint32_t a2, uint32_t a3, uint32_t b0,
                                         uint32_t b1) {
    asm volatile(
        "mma.sync.aligned.m16n8k16.row.col.f32.bf16.bf16.f32 "
        "{%0,%1,%2,%3}, {%4,%5,%6,%7}, {%8,%9}, {%0,%1,%2,%3};"
        : "+f"(d[0]), "+f"(d[1]), "+f"(d[2]), "+f"(d[3])
        : "r"(a0), "r"(a1), "r"(a2), "r"(a3), "r"(b0), "r"(b1));
}

// ---------------- prep_all: weights -> split/padded; vectors ----------------
__device__ __forceinline__ void mma_tile4(const float (*As)[68], const float (*Bs)[68],
                                          int ty, int tx, float acc[4][4]) {
#pragma unroll
    for (int kk = 0; kk < 16; ++kk) {
        float4 av = *reinterpret_cast<const float4*>(&As[kk][ty * 4]);
        float4 bv = *reinterpret_cast<const float4*>(&Bs[kk][tx * 4]);
        float ar[4] = {av.x, av.y, av.z, av.w};
        float br[4] = {bv.x, bv.y, bv.z, bv.w};
#pragma unroll
        for (int i = 0; i < 4; ++i)
#pragma unroll
            for (int j = 0; j < 4; ++j)
                acc[i][j] = fmaf(ar[i], br[j], acc[i][j]);
    }
}

__global__ __launch_bounds__(256) void prep_all(const float* __restrict__ Wq,
                                                const float* __restrict__ bq,
                                                const float* __restrict__ Wk,
                                                const float* __restrict__ bk,
                                                const float* __restrict__ Wv) {
    const float scale = 0.0625f;  // 1/sqrt(256)
    const int blk = blockIdx.x;
    const int t = threadIdx.x;
    if (blk >= 18) {
        // Wv rows -> g_BH1/g_BL1 (padded layout)
        const int rbase = (blk - 18) * 128;
#pragma unroll
        for (int i = 0; i < 16; ++i) {
            int u = t + i * 256;            // 4096 units = 128 rows x 32 kg
            int r = rbase + (u >> 5), kg = u & 31;
            const float* ap = Wv + (size_t)r * DD + kg * 8;
            float4 f0 = *reinterpret_cast<const float4*>(ap);
            float4 f1 = *reinterpret_cast<const float4*>(ap + 4);
            __nv_bfloat16 h0, h1, h2, h3, h4, h5, h6, h7;
            __nv_bfloat16 l0, l1, l2, l3, l4, l5, l6, l7;
            bsplit(f0.x, h0, l0); bsplit(f0.y, h1, l1);
            bsplit(f0.z, h2, l2); bsplit(f0.w, h3, l3);
            bsplit(f1.x, h4, l4); bsplit(f1.y, h5, l5);
            bsplit(f1.z, h6, l6); bsplit(f1.w, h7, l7);
            uint4 vh = make_uint4(bpack(h0, h1), bpack(h2, h3), bpack(h4, h5),
                                  bpack(h6, h7));
            uint4 vl = make_uint4(bpack(l0, l1), bpack(l2, l3), bpack(l4, l5),
                                  bpack(l6, l7));
            *reinterpret_cast<uint4*>(&g_BH1[(size_t)r * KP + kg * 8]) = vh;
            *reinterpret_cast<uint4*>(&g_BL1[(size_t)r * KP + kg * 8]) = vl;
        }
        return;
    }
    if (blk >= 16) {
        if (blk == 16) {
            float s0 = 0.f, s1 = 0.f, s2 = 0.f, s3 = 0.f;
#pragma unroll 16
            for (int k = 0; k < DD; k += 4) {
                s0 = fmaf(Wq[(k + 0) * DD + t], bk[k + 0], s0);
                s1 = fmaf(Wq[(k + 1) * DD + t], bk[k + 1], s1);
                s2 = fmaf(Wq[(k + 2) * DD + t], bk[k + 2], s2);
                s3 = fmaf(Wq[(k + 3) * DD + t], bk[k + 3], s3);
            }
            g_u[t] = scale * ((s0 + s1) + (s2 + s3));
            if (t == 0) {
                float c0 = 0.f, c1 = 0.f;
#pragma unroll 16
                for (int k = 0; k < DD; k += 2) {
                    c0 = fmaf(bq[k], bk[k], c0);
                    c1 = fmaf(bq[k + 1], bk[k + 1], c1);
                }
                g_c = scale * (c0 + c1);
            }
        } else {
            float s0 = 0.f, s1 = 0.f, s2 = 0.f, s3 = 0.f;
#pragma unroll 16
            for (int k = 0; k < DD; k += 4) {
                s0 = fmaf(bq[k + 0], Wk[(k + 0) * DD + t], s0);
                s1 = fmaf(bq[k + 1], Wk[(k + 1) * DD + t], s1);
                s2 = fmaf(bq[k + 2], Wk[(k + 2) * DD + t], s2);
                s3 = fmaf(bq[k + 3], Wk[(k + 3) * DD + t], s3);
            }
            g_b2[t] = scale * ((s0 + s1) + (s2 + s3));
        }
        return;
    }
    // W2 tile = scale * Wq^T @ Wk; store transposed split: BT0[e][d]
    __shared__ float As[16][68];
    __shared__ float Bs[16][68];
    int tx = t % 16, ty = t / 16;
    int d0 = (blk % 4) * 64, e0 = (blk / 4) * 64;
    float acc[4][4] = {};
    for (int k0 = 0; k0 < DD; k0 += 16) {
        float4 a = *reinterpret_cast<const float4*>(Wq + (k0 + ty) * DD + d0 + tx * 4);
        float4 b = *reinterpret_cast<const float4*>(Wk + (k0 + ty) * DD + e0 + tx * 4);
        *reinterpret_cast<float4*>(&As[ty][tx * 4]) = a;
        *reinterpret_cast<float4*>(&Bs[ty][tx * 4]) = b;
        __syncthreads();
        mma_tile4(As, Bs, ty, tx, acc);
        __syncthreads();
    }
#pragma unroll
    for (int i = 0; i < 4; ++i)
#pragma unroll
        for (int j = 0; j < 4; ++j) {
            float v = scale * acc[i][j];
            __nv_bfloat16 h, l;
            bsplit(v, h, l);
            int e = e0 + tx * 4 + j, d = d0 + ty * 4 + i;
            g_BH0[(size_t)e * KP + d] = h;
            g_BL0[(size_t)e * KP + d] = l;
        }
}

// ---------------- unified HMMA GEMM: LDG-staged A, DMA-staged B -------------
// C[4096,256] = A @ B^T (+bias); bf16 split: D = Ahi*Bhi + Ahi*Blo + Alo*Bhi
// tile M=128, N=64, K=256 resident; padded rows 528 B; 512 thr, k-split sets.
// BMODE 0: A = cc (fp32),   B = BH0/BL0, C = g_Qk, bias = g_b2; qb on by==0
// BMODE 1: A = g_wsum,      B = BH1/BL1, C = out,  bias = bv[n]*g_S[m]
#define SM_MB   0
#define SM_BIAS 16
#define SM_U    1024
#define SM_AH   2048
#define SM_AL   (SM_AH + 128 * KPB)
#define SM_BH   (SM_AL + 128 * KPB)
#define SM_BL   (SM_BH + 64 * KPB)
#define MMA_SMEM (SM_BL + 64 * KPB)   // 204800
#define SM_RED  SM_AH
#define TXB     (2 * 64 * KPB)        // B hi+lo bytes

template <int BMODE>
__global__ __launch_bounds__(512) void mma_gemm(const float* __restrict__ Afp,
                                                const float* __restrict__ biasp,
                                                float* __restrict__ Cp) {
    extern __shared__ char dsm[];
    const float* A = (BMODE == 0) ? Afp : g_wsum;
    const __nv_bfloat16* BHg = (BMODE == 0) ? g_BH0 : g_BH1;
    const __nv_bfloat16* BLg = (BMODE == 0) ? g_BL0 : g_BL1;
    const float* bias = (BMODE == 0) ? g_b2 : biasp;
    float* C = (BMODE == 0) ? g_Qk : Cp;

    const int t = threadIdx.x;
    const int w = t >> 5, lane = t & 31;
    const int wset = w >> 3, wp = w & 7;
    const int m0 = blockIdx.x * 128, n0 = blockIdx.y * 64;
    const uint32_t sb = smem_u32(dsm);
    const bool qb_active = (BMODE == 0) && (blockIdx.y == 0);

    if (t == 0)
        asm volatile("mbarrier.init.shared::cta.b64 [%0], 1;" :: "r"(sb + SM_MB)
                     : "memory");
    __syncthreads();
    // issue B DMA first: it hides under A staging below
    if (t == 0) {
        asm volatile("mbarrier.arrive.expect_tx.shared::cta.b64 _, [%0], %1;"
                     :: "r"(sb + SM_MB), "r"((uint32_t)TXB) : "memory");
        asm volatile(
            "cp.async.bulk.shared::cta.global.mbarrier::complete_tx::bytes "
            "[%0], [%1], %2, [%3];"
            :: "r"(sb + SM_BH), "l"(BHg + (size_t)n0 * KP),
               "r"(64 * KPB), "r"(sb + SM_MB) : "memory");
        asm volatile(
            "cp.async.bulk.shared::cta.global.mbarrier::complete_tx::bytes "
            "[%0], [%1], %2, [%3];"
            :: "r"(sb + SM_BL), "l"(BLg + (size_t)n0 * KP),
               "r"(64 * KPB), "r"(sb + SM_MB) : "memory");
    }
    if (t < 64)
        *reinterpret_cast<float*>(dsm + SM_BIAS + t * 4) = bias[n0 + t];
    if (qb_active && t < DD)
        *reinterpret_cast<float*>(dsm + SM_U + t * 4) = g_u[t];
    if (qb_active) __syncthreads();  // s_u visible before staging dots

    // stage A: warp w, iter i -> row w + 16*i; lane -> k-group (8 floats)
    const float* s_u = reinterpret_cast<const float*>(dsm + SM_U);
#pragma unroll
    for (int i = 0; i < 8; ++i) {
        const int r = w + 16 * i;
        const float* ap = A + (size_t)(m0 + r) * DD + lane * 8;
        float4 f0 = *reinterpret_cast<const float4*>(ap);
        float4 f1 = *reinterpret_cast<const float4*>(ap + 4);
        if (qb_active) {
            const float* uu = s_u + lane * 8;
            float p = f0.x * uu[0] + f0.y * uu[1] + f0.z * uu[2] + f0.w * uu[3] +
                      f1.x * uu[4] + f1.y * uu[5] + f1.z * uu[6] + f1.w * uu[7];
#pragma unroll
            for (int o = 16; o; o >>= 1) p += __shfl_xor_sync(0xffffffffu, p, o);
            if (lane == 0) g_qb[m0 + r] = p + g_c;
        }
        __nv_bfloat16 h0, h1, h2, h3, h4, h5, h6, h7;
        __nv_bfloat16 l0, l1, l2, l3, l4, l5, l6, l7;
        bsplit(f0.x, h0, l0); bsplit(f0.y, h1, l1);
        bsplit(f0.z, h2, l2); bsplit(f0.w, h3, l3);
        bsplit(f1.x, h4, l4); bsplit(f1.y, h5, l5);
        bsplit(f1.z, h6, l6); bsplit(f1.w, h7, l7);
        uint4 vh = make_uint4(bpack(h0, h1), bpack(h2, h3), bpack(h4, h5),
                              bpack(h6, h7));
        uint4 vl = make_uint4(bpack(l0, l1), bpack(l2, l3), bpack(l4, l5),
                              bpack(l6, l7));
        *reinterpret_cast<uint4*>(dsm + SM_AH + r * KPB + lane * 16) = vh;
        *reinterpret_cast<uint4*>(dsm + SM_AL + r * KPB + lane * 16) = vl;
    }
    __syncthreads();
    // wait for B DMA (usually already complete)
    asm volatile(
        "{ .reg .pred P;\n"
        "WL%=: mbarrier.try_wait.parity.acquire.cta.shared::cta.b64 P, [%0], 0;\n"
        "@!P bra WL%=; }"
        :: "r"(sb + SM_MB) : "memory");

    // per-lane ldmatrix base offsets (warp position = wp)
    const uint32_t laneA = (16 * wp + (lane & 15)) * KPB + (lane >> 4) * 16;
    const uint32_t laneB =
        (((lane >> 4) * 8) + (lane & 7)) * KPB + ((lane >> 3) & 1) * 16;

    float d[8][4];
#pragma unroll
    for (int v = 0; v < 8; ++v)
#pragma unroll
        for (int i = 0; i < 4; ++i) d[v][i] = 0.f;

    const int j0 = wset * 8;
#pragma unroll
    for (int jj = 0; jj < 8; ++jj) {
        const uint32_t koff = (uint32_t)(j0 + jj) * 32;  // 16 bf16 = 32 B/step
        uint32_t ah0, ah1, ah2, ah3, al0, al1, al2, al3;
        ldsm_x4(sb + SM_AH + laneA + koff, ah0, ah1, ah2, ah3);
        ldsm_x4(sb + SM_AL + laneA + koff, al0, al1, al2, al3);
#pragma unroll
        for (int p = 0; p < 4; ++p) {
            const uint32_t prow = p * 16 * KPB;
            uint32_t bh0, bh1, bh2, bh3, bl0, bl1, bl2, bl3;
            ldsm_x4(sb + SM_BH + prow + laneB + koff, bh0, bh1, bh2, bh3);
            ldsm_x4(sb + SM_BL + prow + laneB + koff, bl0, bl1, bl2, bl3);
            mma_bf16(d[2 * p], ah0, ah1, ah2, ah3, bh0, bh1);
            mma_bf16(d[2 * p], al0, al1, al2, al3, bh0, bh1);
            mma_bf16(d[2 * p], ah0, ah1, ah2, ah3, bl0, bl1);
            mma_bf16(d[2 * p + 1], ah0, ah1, ah2, ah3, bh2, bh3);
            mma_bf16(d[2 * p + 1], al0, al1, al2, al3, bh2, bh3);
            mma_bf16(d[2 * p + 1], ah0, ah1, ah2, ah3, bl2, bl3);
        }
    }
    __syncthreads();  // A region dead; reuse as reduction buffer

    if (wset == 1) {
        float4* red = reinterpret_cast<float4*>(dsm + SM_RED) +
                      (size_t)(wp * 32 + lane) * 8;
#pragma unroll
        for (int v = 0; v < 8; ++v)
            red[v] = make_float4(d[v][0], d[v][1], d[v][2], d[v][3]);
    }
    __syncthreads();

    if (wset == 0) {
        const float4* red = reinterpret_cast<const float4*>(dsm + SM_RED) +
                            (size_t)(wp * 32 + lane) * 8;
        const float* s_bias = reinterpret_cast<const float*>(dsm + SM_BIAS);
        const int gm = m0 + 16 * wp + (lane >> 2);
        const int cn = 2 * (lane & 3);
        float sv0 = 1.f, sv1 = 1.f;
        if (BMODE == 1) {
            sv0 = g_S[gm];
            sv1 = g_S[gm + 8];
        }
#pragma unroll
        for (int v = 0; v < 8; ++v) {
            float4 r = red[v];
            const int n = 8 * v + cn;
            const float b0 = s_bias[n], b1 = s_bias[n + 1];
            float2 o0 = make_float2(d[v][0] + r.x + b0 * sv0,
                                    d[v][1] + r.y + b1 * sv0);
            float2 o1 = make_float2(d[v][2] + r.z + b0 * sv1,
                                    d[v][3] + r.w + b1 * sv1);
            *reinterpret_cast<float2*>(C + (size_t)gm * DD + n0 + n) = o0;
            *reinterpret_cast<float2*>(C + (size_t)(gm + 8) * DD + n0 + n) = o1;
        }
    }
}

// ---------------- attn v7: two independent 256-thread halves per CTA --------
__global__ __launch_bounds__(512) void attn_v7(const float* __restrict__ anchor,
                                               const float* __restrict__ sims) {
    extern __shared__ float sm[];
    float* sP = sm + NBUF * AA * DD;  // [2 halves][8 warps][256]
    __shared__ float s_adj[2][AA];
    __shared__ __align__(8) unsigned long long mbar[NBUF];

    const int t = threadIdx.x;
    const int half = t >> 8;
    const int th = t & 255;
    const int w = th >> 5;
    const int lane = t & 31;
    const int cta = blockIdx.x;
    const int iters = (NROWS - cta + NCTA - 1) / NCTA;

    uint32_t mb_base, sA_base;
    asm("{ .reg .u64 x; cvta.to.shared.u64 x, %1; cvt.u32.u64 %0, x; }"
        : "=r"(mb_base) : "l"(mbar));
    asm("{ .reg .u64 x; cvta.to.shared.u64 x, %1; cvt.u32.u64 %0, x; }"
        : "=r"(sA_base) : "l"(sm));

    if (t == 0) {
#pragma unroll
        for (int j = 0; j < NBUF; ++j)
            asm volatile("mbarrier.init.shared::cta.b64 [%0], 1;"
                         :: "r"(mb_base + j * 8));
    }
    __syncthreads();
    if (t == 0) {
#pragma unroll
        for (int j = 0; j < NBUF; ++j)
            if (j < iters) {
                uint32_t mb = mb_base + j * 8;
                asm volatile("mbarrier.arrive.expect_tx.shared::cta.b64 _, [%0], %1;"
                             :: "r"(mb), "r"(65536));
                asm volatile(
                    "cp.async.bulk.shared::cta.global.mbarrier::complete_tx::bytes "
                    "[%0], [%1], %2, [%3];"
                    :: "r"(sA_base + j * 65536),
                       "l"(anchor + (size_t)(cta + j * NCTA) * AA * DD),
                       "r"(65536), "r"(mb) : "memory");
            }
    }
    __syncthreads();

    const int bar_id = 1 + half;

    for (int it = half; it < iters; it += 2) {
        const int row = cta + it * NCTA;
        const int b = it % NBUF;
        const float* sA = sm + b * AA * DD;

        const float4* qg = reinterpret_cast<const float4*>(g_Qk + (size_t)row * DD);
        float4 q0 = qg[lane], q1 = qg[lane + 32];
        float qb = g_qb[row];
        float simv = (lane < 8) ? sims[row * AA + w + 8 * lane] : 0.f;

        {
            uint32_t mb = mb_base + b * 8;
            int par = (it / NBUF) & 1;
            asm volatile(
                "{ .reg .pred P;\n"
                "WL%=: mbarrier.try_wait.parity.acquire.cta.shared::cta.b64 P, [%0], %1;\n"
                "@!P bra WL%=; }"
                :: "r"(mb), "r"(par) : "memory");
        }

        float4 x0[8], x1[8];
        float val = 0.f;
#pragma unroll
        for (int j = 0; j < 8; ++j) {
            const int a = w + 8 * j;
            const float4* a4 = reinterpret_cast<const float4*>(sA + a * DD);
            x0[j] = a4[lane];
            x1[j] = a4[lane + 32];
            float s = q0.x * x0[j].x + q0.y * x0[j].y + q0.z * x0[j].z +
                      q0.w * x0[j].w + q1.x * x1[j].x + q1.y * x1[j].y +
                      q1.z * x1[j].z + q1.w * x1[j].w;
#pragma unroll
            for (int o = 16; o; o >>= 1) s += __shfl_xor_sync(0xffffffffu, s, o);
            if (lane == j) val = s + qb + simv;
        }
        if (lane < 8) s_adj[half][w + 8 * lane] = val;

        asm volatile("bar.sync %0, 256;" :: "r"(bar_id) : "memory");

        if (th == 0 && it + NBUF < iters) {
            uint32_t mb = mb_base + b * 8;
            asm volatile("mbarrier.arrive.expect_tx.shared::cta.b64 _, [%0], %1;"
                         :: "r"(mb), "r"(65536));
            asm volatile(
                "cp.async.bulk.shared::cta.global.mbarrier::complete_tx::bytes "
                "[%0], [%1], %2, [%3];"
                :: "r"(sA_base + b * 65536),
                   "l"(anchor + (size_t)(row + NBUF * NCTA) * AA * DD),
                   "r"(65536), "r"(mb) : "memory");
        }

        float p0, p1;
        {
            float v0 = s_adj[half][lane], v1 = s_adj[half][lane + 32];
            float sum = v0 + v1;
            float mx = fmaxf(v0, v1);
#pragma unroll
            for (int o = 16; o; o >>= 1) {
                sum += __shfl_xor_sync(0xffffffffu, sum, o);
                mx = fmaxf(mx, __shfl_xor_sync(0xffffffffu, mx, o));
            }
            if (sum != 0.0f) {
                float e0 = __expf(v0 - mx), e1 = __expf(v1 - mx);
                float es = e0 + e1;
#pragma unroll
                for (int o = 16; o; o >>= 1) es += __shfl_xor_sync(0xffffffffu, es, o);
                float inv = 1.0f / es;
                p0 = e0 * inv;
                p1 = e1 * inv;
                if (th == 0) g_S[row] = 1.0f;
            } else {
                p0 = v0;
                p1 = v1;
                if (th == 0) g_S[row] = 0.0f;
            }
        }
        float pa[8];
#pragma unroll
        for (int j = 0; j < 4; ++j)
            pa[j] = __shfl_sync(0xffffffffu, p0, w + 8 * j);
#pragma unroll
        for (int j = 4; j < 8; ++j)
            pa[j] = __shfl_sync(0xffffffffu, p1, w + 8 * j - 32);

        float4 acc0 = make_float4(0.f, 0.f, 0.f, 0.f);
        float4 acc1 = make_float4(0.f, 0.f, 0.f, 0.f);
#pragma unroll
        for (int j = 0; j < 8; ++j) {
            acc0.x = fmaf(pa[j], x0[j].x, acc0.x);
            acc0.y = fmaf(pa[j], x0[j].y, acc0.y);
            acc0.z = fmaf(pa[j], x0[j].z, acc0.z);
            acc0.w = fmaf(pa[j], x0[j].w, acc0.w);
            acc1.x = fmaf(pa[j], x1[j].x, acc1.x);
            acc1.y = fmaf(pa[j], x1[j].y, acc1.y);
            acc1.z = fmaf(pa[j], x1[j].z, acc1.z);
            acc1.w = fmaf(pa[j], x1[j].w, acc1.w);
        }
        float* myP = sP + (half * 8 + w) * DD;
        *reinterpret_cast<float4*>(myP + lane * 4) = acc0;
        *reinterpret_cast<float4*>(myP + 128 + lane * 4) = acc1;

        asm volatile("bar.sync %0, 256;" :: "r"(bar_id) : "memory");

        {
            const float* hp = sP + half * 8 * DD;
            float a = 0.f;
#pragma unroll
            for (int i = 0; i < 8; ++i) a += hp[i * DD + th];
            g_wsum[(size_t)row * DD + th] = a;
        }
    }
}

// ---------------- launch ----------------------------------------------------
extern "C" void kernel_launch(void* const* d_in, const int* in_sizes, int n_in,
                              void* d_out, int out_size) {
    const float* cc     = (const float*)d_in[0];
    const float* anchor = (const float*)d_in[1];
    const float* sims   = (const float*)d_in[2];
    const float* Wq     = (const float*)d_in[3];
    const float* bq     = (const float*)d_in[4];
    const float* Wk     = (const float*)d_in[5];
    const float* bk     = (const float*)d_in[6];
    const float* Wv     = (const float*)d_in[7];
    const float* bv     = (const float*)d_in[8];
    float* out = (float*)d_out;

    const int smem_attn = (NBUF * AA * DD + 16 * DD) * (int)sizeof(float);  // 208 KB
    cudaFuncSetAttribute(attn_v7, cudaFuncAttributeMaxDynamicSharedMemorySize,
                         smem_attn);
    cudaFuncSetAttribute(mma_gemm<0>, cudaFuncAttributeMaxDynamicSharedMemorySize,
                         MMA_SMEM);
    cudaFuncSetAttribute(mma_gemm<1>, cudaFuncAttributeMaxDynamicSharedMemorySize,
                         MMA_SMEM);

    prep_all<<<20, 256>>>(Wq, bq, Wk, bk, Wv);
    mma_gemm<0><<<dim3(32, 4), 512, MMA_SMEM>>>(cc, nullptr, nullptr);
    attn_v7<<<NCTA, 512, smem_attn>>>(anchor, sims);
    mma_gemm<1><<<dim3(32, 4), 512, MMA_SMEM>>>(nullptr, bv, out);
}

// round 16
// speedup vs baseline: 1.2295x; 1.0060x over previous
#include <cuda_runtime.h>
#include <cuda_bf16.h>
#include <math.h>
#include <stdint.h>

#define DD 256
#define AA 64
#define NROWS 4096   // B*N
#define NCTA 148     // persistent CTAs for attn
#define NBUF 3       // pipeline depth
#define KP 264       // padded row length (bf16 elems); 528 B rows
#define KPB 528

// ---------------- scratch (device globals; no allocation allowed) ----------
__device__ float g_b2[DD];           // scale * bq @ Wk   (bias for Qk)
__device__ float g_u[DD];            // scale * Wq^T @ bk
__device__ float g_c;                // scale * bq . bk
__device__ float g_Qk[NROWS * DD];   // cc @ W2 + b2  (fp32, read by attn)
__device__ float g_qb[NROWS];        // cc_row . g_u + g_c
__device__ float g_wsum[NROWS * DD]; // sum_a p[a] * anchor[a,:]
__device__ float g_S[NROWS];         // softmax flag
// pre-split, pre-padded bf16 weight matrices (row stride KP, [n][k])
__device__ __align__(16) __nv_bfloat16 g_BH0[DD * KP];  // W2^T hi
__device__ __align__(16) __nv_bfloat16 g_BL0[DD * KP];  // W2^T lo
__device__ __align__(16) __nv_bfloat16 g_BH1[DD * KP];  // Wv hi
__device__ __align__(16) __nv_bfloat16 g_BL1[DD * KP];  // Wv lo

// ---------------- small helpers ---------------------------------------------
__device__ __forceinline__ uint32_t smem_u32(const void* p) {
    uint32_t a;
    asm("{ .reg .u64 x; cvta.to.shared.u64 x, %1; cvt.u32.u64 %0, x; }"
        : "=r"(a) : "l"(p));
    return a;
}
__device__ __forceinline__ void bsplit(float x, __nv_bfloat16& h, __nv_bfloat16& l) {
    h = __float2bfloat16(x);
    l = __float2bfloat16(x - __bfloat162float(h));
}
__device__ __forceinline__ uint32_t bpack(__nv_bfloat16 a, __nv_bfloat16 b) {
    __nv_bfloat162 v;
    v.x = a;
    v.y = b;
    return *reinterpret_cast<uint32_t*>(&v);
}

// ---------------- mma / ldmatrix wrappers ------------------------------------
__device__ __forceinline__ void ldsm_x4(uint32_t addr, uint32_t& r0, uint32_t& r1,
                                        uint32_t& r2, uint32_t& r3) {
    asm volatile("ldmatrix.sync.aligned.m8n8.x4.shared.b16 {%0,%1,%2,%3}, [%4];"
                 : "=r"(r0), "=r"(r1), "=r"(r2), "=r"(r3) : "r"(addr));
}
__device__ __forceinline__ void mma_bf16(float* d, uint32_t a0, uint32_t a1,
                                         uint32_t a2, uint32_t a3, uint32_t b0,
                                         uint32_t b1) {
    asm volatile(
        "mma.sync.aligned.m16n8k16.row.col.f32.bf16.bf16.f32 "
        "{%0,%1,%2,%3}, {%4,%5,%6,%7}, {%8,%9}, {%0,%1,%2,%3};"
        : "+f"(d[0]), "+f"(d[1]), "+f"(d[2]), "+f"(d[3])
        : "r"(a0), "r"(a1), "r"(a2), "r"(a3), "r"(b0), "r"(b1));
}

// ---------------- prep_all: weights -> split/padded; vectors ----------------
__device__ __forceinline__ void mma_tile4(const float (*As)[68], const float (*Bs)[68],
                                          int ty, int tx, float acc[4][4]) {
#pragma unroll
    for (int kk = 0; kk < 16; ++kk) {
        float4 av = *reinterpret_cast<const float4*>(&As[kk][ty * 4]);
        float4 bv = *reinterpret_cast<const float4*>(&Bs[kk][tx * 4]);
        float ar[4] = {av.x, av.y, av.z, av.w};
        float br[4] = {bv.x, bv.y, bv.z, bv.w};
#pragma unroll
        for (int i = 0; i < 4; ++i)
#pragma unroll
            for (int j = 0; j < 4; ++j)
                acc[i][j] = fmaf(ar[i], br[j], acc[i][j]);
    }
}

__global__ __launch_bounds__(256) void prep_all(const float* __restrict__ Wq,
                                                const float* __restrict__ bq,
                                                const float* __restrict__ Wk,
                                                const float* __restrict__ bk,
                                                const float* __restrict__ Wv) {
    const float scale = 0.0625f;  // 1/sqrt(256)
    const int blk = blockIdx.x;
    const int t = threadIdx.x;
    if (blk >= 18) {
        // Wv rows -> g_BH1/g_BL1 (padded layout)
        const int rbase = (blk - 18) * 128;
#pragma unroll
        for (int i = 0; i < 16; ++i) {
            int u = t + i * 256;            // 4096 units = 128 rows x 32 kg
            int r = rbase + (u >> 5), kg = u & 31;
            const float* ap = Wv + (size_t)r * DD + kg * 8;
            float4 f0 = *reinterpret_cast<const float4*>(ap);
            float4 f1 = *reinterpret_cast<const float4*>(ap + 4);
            __nv_bfloat16 h0, h1, h2, h3, h4, h5, h6, h7;
            __nv_bfloat16 l0, l1, l2, l3, l4, l5, l6, l7;
            bsplit(f0.x, h0, l0); bsplit(f0.y, h1, l1);
            bsplit(f0.z, h2, l2); bsplit(f0.w, h3, l3);
            bsplit(f1.x, h4, l4); bsplit(f1.y, h5, l5);
            bsplit(f1.z, h6, l6); bsplit(f1.w, h7, l7);
            uint4 vh = make_uint4(bpack(h0, h1), bpack(h2, h3), bpack(h4, h5),
                                  bpack(h6, h7));
            uint4 vl = make_uint4(bpack(l0, l1), bpack(l2, l3), bpack(l4, l5),
                                  bpack(l6, l7));
            *reinterpret_cast<uint4*>(&g_BH1[(size_t)r * KP + kg * 8]) = vh;
            *reinterpret_cast<uint4*>(&g_BL1[(size_t)r * KP + kg * 8]) = vl;
        }
        return;
    }
    if (blk >= 16) {
        if (blk == 16) {
            float s0 = 0.f, s1 = 0.f, s2 = 0.f, s3 = 0.f;
#pragma unroll 16
            for (int k = 0; k < DD; k += 4) {
                s0 = fmaf(Wq[(k + 0) * DD + t], bk[k + 0], s0);
                s1 = fmaf(Wq[(k + 1) * DD + t], bk[k + 1], s1);
                s2 = fmaf(Wq[(k + 2) * DD + t], bk[k + 2], s2);
                s3 = fmaf(Wq[(k + 3) * DD + t], bk[k + 3], s3);
            }
            g_u[t] = scale * ((s0 + s1) + (s2 + s3));
            if (t == 0) {
                float c0 = 0.f, c1 = 0.f;
#pragma unroll 16
                for (int k = 0; k < DD; k += 2) {
                    c0 = fmaf(bq[k], bk[k], c0);
                    c1 = fmaf(bq[k + 1], bk[k + 1], c1);
                }
                g_c = scale * (c0 + c1);
            }
        } else {
            float s0 = 0.f, s1 = 0.f, s2 = 0.f, s3 = 0.f;
#pragma unroll 16
            for (int k = 0; k < DD; k += 4) {
                s0 = fmaf(bq[k + 0], Wk[(k + 0) * DD + t], s0);
                s1 = fmaf(bq[k + 1], Wk[(k + 1) * DD + t], s1);
                s2 = fmaf(bq[k + 2], Wk[(k + 2) * DD + t], s2);
                s3 = fmaf(bq[k + 3], Wk[(k + 3) * DD + t], s3);
            }
            g_b2[t] = scale * ((s0 + s1) + (s2 + s3));
        }
        return;
    }
    // W2 tile = scale * Wq^T @ Wk; store transposed split: BT0[e][d]
    __shared__ float As[16][68];
    __shared__ float Bs[16][68];
    int tx = t % 16, ty = t / 16;
    int d0 = (blk % 4) * 64, e0 = (blk / 4) * 64;
    float acc[4][4] = {};
    for (int k0 = 0; k0 < DD; k0 += 16) {
        float4 a = *reinterpret_cast<const float4*>(Wq + (k0 + ty) * DD + d0 + tx * 4);
        float4 b = *reinterpret_cast<const float4*>(Wk + (k0 + ty) * DD + e0 + tx * 4);
        *reinterpret_cast<float4*>(&As[ty][tx * 4]) = a;
        *reinterpret_cast<float4*>(&Bs[ty][tx * 4]) = b;
        __syncthreads();
        mma_tile4(As, Bs, ty, tx, acc);
        __syncthreads();
    }
#pragma unroll
    for (int i = 0; i < 4; ++i)
#pragma unroll
        for (int j = 0; j < 4; ++j) {
            float v = scale * acc[i][j];
            __nv_bfloat16 h, l;
            bsplit(v, h, l);
            int e = e0 + tx * 4 + j, d = d0 + ty * 4 + i;
            g_BH0[(size_t)e * KP + d] = h;
            g_BL0[(size_t)e * KP + d] = l;
        }
}

// ---------------- HMMA GEMM v4: decoupled k-split sets ----------------------
// C[4096,256] = A @ B^T (+bias); bf16 split: D = Ahi*Bhi + Ahi*Blo + Alo*Bhi
// tile M=128, N=64, K=256; 512 thr; set s stages+computes its own k-half.
// BMODE 0: A = cc (fp32),   B = BH0/BL0, C = g_Qk, bias = g_b2; qb on by==0
// BMODE 1: A = g_wsum,      B = BH1/BL1, C = out,  bias = bv[n]*g_S[m]
#define SM_MB   0
#define SM_BIAS 16
#define SM_U    1024
#define SM_QB   2048                  // float[2][128]
#define SM_AH   4096
#define SM_AL   (SM_AH + 128 * KPB)
#define SM_BH   (SM_AL + 128 * KPB)
#define SM_BL   (SM_BH + 64 * KPB)
#define MMA_SMEM (SM_BL + 64 * KPB)   // 206848
#define SM_RED  SM_AH
#define TXB     (2 * 64 * KPB)        // B hi+lo bytes

template <int BMODE>
__global__ __launch_bounds__(512) void mma_gemm(const float* __restrict__ Afp,
                                                const float* __restrict__ biasp,
                                                float* __restrict__ Cp) {
    extern __shared__ char dsm[];
    const float* A = (BMODE == 0) ? Afp : g_wsum;
    const __nv_bfloat16* BHg = (BMODE == 0) ? g_BH0 : g_BH1;
    const __nv_bfloat16* BLg = (BMODE == 0) ? g_BL0 : g_BL1;
    const float* bias = (BMODE == 0) ? g_b2 : biasp;
    float* C = (BMODE == 0) ? g_Qk : Cp;

    const int t = threadIdx.x;
    const int w = t >> 5, lane = t & 31;
    const int wset = w >> 3, wp = w & 7;
    const int m0 = blockIdx.x * 128, n0 = blockIdx.y * 64;
    const uint32_t sb = smem_u32(dsm);
    const bool qb_active = (BMODE == 0) && (blockIdx.y == 0);

    if (t == 0)
        asm volatile("mbarrier.init.shared::cta.b64 [%0], 1;" :: "r"(sb + SM_MB)
                     : "memory");
    __syncthreads();
    // issue B DMA first: hides under A staging
    if (t == 0) {
        asm volatile("mbarrier.arrive.expect_tx.shared::cta.b64 _, [%0], %1;"
                     :: "r"(sb + SM_MB), "r"((uint32_t)TXB) : "memory");
        asm volatile(
            "cp.async.bulk.shared::cta.global.mbarrier::complete_tx::bytes "
            "[%0], [%1], %2, [%3];"
            :: "r"(sb + SM_BH), "l"(BHg + (size_t)n0 * KP),
               "r"(64 * KPB), "r"(sb + SM_MB) : "memory");
        asm volatile(
            "cp.async.bulk.shared::cta.global.mbarrier::complete_tx::bytes "
            "[%0], [%1], %2, [%3];"
            :: "r"(sb + SM_BL), "l"(BLg + (size_t)n0 * KP),
               "r"(64 * KPB), "r"(sb + SM_MB) : "memory");
    }
    if (t < 64)
        *reinterpret_cast<float*>(dsm + SM_BIAS + t * 4) = bias[n0 + t];
    if (qb_active) {
        if (t < DD) *reinterpret_cast<float*>(dsm + SM_U + t * 4) = g_u[t];
        __syncthreads();  // s_u visible to both sets before staging dots
    }

    // ---- per-set A staging: set s covers ALL 128 rows, its 16 kg half ------
    // unit: rl = i*2 + (lane>>4), kg_local = lane&15; row = wp*16 + rl
    const float* s_u = reinterpret_cast<const float*>(dsm + SM_U);
    float* s_qbp = reinterpret_cast<float*>(dsm + SM_QB);
    const int kg0 = wset * 16;  // k-group offset of this set's half
#pragma unroll
    for (int i = 0; i < 8; ++i) {
        const int rl = i * 2 + (lane >> 4);
        const int r = wp * 16 + rl;
        const int kg = kg0 + (lane & 15);
        const float* ap = A + (size_t)(m0 + r) * DD + kg * 8;
        float4 f0 = *reinterpret_cast<const float4*>(ap);
        float4 f1 = *reinterpret_cast<const float4*>(ap + 4);
        if (qb_active) {
            const float* uu = s_u + kg * 8;
            float p = f0.x * uu[0] + f0.y * uu[1] + f0.z * uu[2] + f0.w * uu[3] +
                      f1.x * uu[4] + f1.y * uu[5] + f1.z * uu[6] + f1.w * uu[7];
            p += __shfl_xor_sync(0xffffffffu, p, 8);
            p += __shfl_xor_sync(0xffffffffu, p, 4);
            p += __shfl_xor_sync(0xffffffffu, p, 2);
            p += __shfl_xor_sync(0xffffffffu, p, 1);
            if ((lane & 15) == 0) s_qbp[wset * 128 + r] = p;
        }
        __nv_bfloat16 h0, h1, h2, h3, h4, h5, h6, h7;
        __nv_bfloat16 l0, l1, l2, l3, l4, l5, l6, l7;
        bsplit(f0.x, h0, l0); bsplit(f0.y, h1, l1);
        bsplit(f0.z, h2, l2); bsplit(f0.w, h3, l3);
        bsplit(f1.x, h4, l4); bsplit(f1.y, h5, l5);
        bsplit(f1.z, h6, l6); bsplit(f1.w, h7, l7);
        uint4 vh = make_uint4(bpack(h0, h1), bpack(h2, h3), bpack(h4, h5),
                              bpack(h6, h7));
        uint4 vl = make_uint4(bpack(l0, l1), bpack(l2, l3), bpack(l4, l5),
                              bpack(l6, l7));
        *reinterpret_cast<uint4*>(dsm + SM_AH + r * KPB + kg * 16) = vh;
        *reinterpret_cast<uint4*>(dsm + SM_AL + r * KPB + kg * 16) = vl;
    }
    // per-set ordering: this set's A half is staged (by this set's 256 thr)
    asm volatile("bar.sync %0, 256;" :: "r"(1 + wset) : "memory");
    // wait for B DMA (usually complete by now)
    asm volatile(
        "{ .reg .pred P;\n"
        "WL%=: mbarrier.try_wait.parity.acquire.cta.shared::cta.b64 P, [%0], 0;\n"
        "@!P bra WL%=; }"
        :: "r"(sb + SM_MB) : "memory");

    // ---- mainloop: set s runs k-steps j0..j0+7 with A prefetch -------------
    const uint32_t laneA = (16 * wp + (lane & 15)) * KPB + (lane >> 4) * 16;
    const uint32_t laneB =
        (((lane >> 4) * 8) + (lane & 7)) * KPB + ((lane >> 3) & 1) * 16;

    float d[8][4];
#pragma unroll
    for (int v = 0; v < 8; ++v)
#pragma unroll
        for (int i = 0; i < 4; ++i) d[v][i] = 0.f;

    const int j0 = wset * 8;
    uint32_t ah0, ah1, ah2, ah3, al0, al1, al2, al3;
    ldsm_x4(sb + SM_AH + laneA + (uint32_t)j0 * 32, ah0, ah1, ah2, ah3);
    ldsm_x4(sb + SM_AL + laneA + (uint32_t)j0 * 32, al0, al1, al2, al3);
#pragma unroll
    for (int jj = 0; jj < 8; ++jj) {
        const uint32_t koff = (uint32_t)(j0 + jj) * 32;
        uint32_t nh0, nh1, nh2, nh3, nl0, nl1, nl2, nl3;
        if (jj < 7) {
            ldsm_x4(sb + SM_AH + laneA + koff + 32, nh0, nh1, nh2, nh3);
            ldsm_x4(sb + SM_AL + laneA + koff + 32, nl0, nl1, nl2, nl3);
        }
#pragma unroll
        for (int p = 0; p < 4; ++p) {
            const uint32_t prow = p * 16 * KPB;
            uint32_t bh0, bh1, bh2, bh3, bl0, bl1, bl2, bl3;
            ldsm_x4(sb + SM_BH + prow + laneB + koff, bh0, bh1, bh2, bh3);
            ldsm_x4(sb + SM_BL + prow + laneB + koff, bl0, bl1, bl2, bl3);
            mma_bf16(d[2 * p], ah0, ah1, ah2, ah3, bh0, bh1);
            mma_bf16(d[2 * p], al0, al1, al2, al3, bh0, bh1);
            mma_bf16(d[2 * p], ah0, ah1, ah2, ah3, bl0, bl1);
            mma_bf16(d[2 * p + 1], ah0, ah1, ah2, ah3, bh2, bh3);
            mma_bf16(d[2 * p + 1], al0, al1, al2, al3, bh2, bh3);
            mma_bf16(d[2 * p + 1], ah0, ah1, ah2, ah3, bl2, bl3);
        }
        if (jj < 7) {
            ah0 = nh0; ah1 = nh1; ah2 = nh2; ah3 = nh3;
            al0 = nl0; al1 = nl1; al2 = nl2; al3 = nl3;
        }
    }
    __syncthreads();  // both sets done; A region dead -> reduction buffer

    if (qb_active && t < 128)
        g_qb[m0 + t] = s_qbp[t] + s_qbp[128 + t] + g_c;

    if (wset == 1) {
        float4* red = reinterpret_cast<float4*>(dsm + SM_RED) +
                      (size_t)(wp * 32 + lane) * 8;
#pragma unroll
        for (int v = 0; v < 8; ++v)
            red[v] = make_float4(d[v][0], d[v][1], d[v][2], d[v][3]);
    }
    __syncthreads();

    if (wset == 0) {
        const float4* red = reinterpret_cast<const float4*>(dsm + SM_RED) +
                            (size_t)(wp * 32 + lane) * 8;
        const float* s_bias = reinterpret_cast<const float*>(dsm + SM_BIAS);
        const int gm = m0 + 16 * wp + (lane >> 2);
        const int cn = 2 * (lane & 3);
        float sv0 = 1.f, sv1 = 1.f;
        if (BMODE == 1) {
            sv0 = g_S[gm];
            sv1 = g_S[gm + 8];
        }
#pragma unroll
        for (int v = 0; v < 8; ++v) {
            float4 r = red[v];
            const int n = 8 * v + cn;
            const float b0 = s_bias[n], b1 = s_bias[n + 1];
            float2 o0 = make_float2(d[v][0] + r.x + b0 * sv0,
                                    d[v][1] + r.y + b1 * sv0);
            float2 o1 = make_float2(d[v][2] + r.z + b0 * sv1,
                                    d[v][3] + r.w + b1 * sv1);
            *reinterpret_cast<float2*>(C + (size_t)gm * DD + n0 + n) = o0;
            *reinterpret_cast<float2*>(C + (size_t)(gm + 8) * DD + n0 + n) = o1;
        }
    }
}

// ---------------- attn v7: two independent 256-thread halves per CTA --------
__global__ __launch_bounds__(512) void attn_v7(const float* __restrict__ anchor,
                                               const float* __restrict__ sims) {
    extern __shared__ float sm[];
    float* sP = sm + NBUF * AA * DD;  // [2 halves][8 warps][256]
    __shared__ float s_adj[2][AA];
    __shared__ __align__(8) unsigned long long mbar[NBUF];

    const int t = threadIdx.x;
    const int half = t >> 8;
    const int th = t & 255;
    const int w = th >> 5;
    const int lane = t & 31;
    const int cta = blockIdx.x;
    const int iters = (NROWS - cta + NCTA - 1) / NCTA;

    uint32_t mb_base, sA_base;
    asm("{ .reg .u64 x; cvta.to.shared.u64 x, %1; cvt.u32.u64 %0, x; }"
        : "=r"(mb_base) : "l"(mbar));
    asm("{ .reg .u64 x; cvta.to.shared.u64 x, %1; cvt.u32.u64 %0, x; }"
        : "=r"(sA_base) : "l"(sm));

    if (t == 0) {
#pragma unroll
        for (int j = 0; j < NBUF; ++j)
            asm volatile("mbarrier.init.shared::cta.b64 [%0], 1;"
                         :: "r"(mb_base + j * 8));
    }
    __syncthreads();
    if (t == 0) {
#pragma unroll
        for (int j = 0; j < NBUF; ++j)
            if (j < iters) {
                uint32_t mb = mb_base + j * 8;
                asm volatile("mbarrier.arrive.expect_tx.shared::cta.b64 _, [%0], %1;"
                             :: "r"(mb), "r"(65536));
                asm volatile(
                    "cp.async.bulk.shared::cta.global.mbarrier::complete_tx::bytes "
                    "[%0], [%1], %2, [%3];"
                    :: "r"(sA_base + j * 65536),
                       "l"(anchor + (size_t)(cta + j * NCTA) * AA * DD),
                       "r"(65536), "r"(mb) : "memory");
            }
    }
    __syncthreads();

    const int bar_id = 1 + half;

    for (int it = half; it < iters; it += 2) {
        const int row = cta + it * NCTA;
        const int b = it % NBUF;
        const float* sA = sm + b * AA * DD;

        const float4* qg = reinterpret_cast<const float4*>(g_Qk + (size_t)row * DD);
        float4 q0 = qg[lane], q1 = qg[lane + 32];
        float qb = g_qb[row];
        float simv = (lane < 8) ? sims[row * AA + w + 8 * lane] : 0.f;

        {
            uint32_t mb = mb_base + b * 8;
            int par = (it / NBUF) & 1;
            asm volatile(
                "{ .reg .pred P;\n"
                "WL%=: mbarrier.try_wait.parity.acquire.cta.shared::cta.b64 P, [%0], %1;\n"
                "@!P bra WL%=; }"
                :: "r"(mb), "r"(par) : "memory");
        }

        float4 x0[8], x1[8];
        float val = 0.f;
#pragma unroll
        for (int j = 0; j < 8; ++j) {
            const int a = w + 8 * j;
            const float4* a4 = reinterpret_cast<const float4*>(sA + a * DD);
            x0[j] = a4[lane];
            x1[j] = a4[lane + 32];
            float s = q0.x * x0[j].x + q0.y * x0[j].y + q0.z * x0[j].z +
                      q0.w * x0[j].w + q1.x * x1[j].x + q1.y * x1[j].y +
                      q1.z * x1[j].z + q1.w * x1[j].w;
#pragma unroll
            for (int o = 16; o; o >>= 1) s += __shfl_xor_sync(0xffffffffu, s, o);
            if (lane == j) val = s + qb + simv;
        }
        if (lane < 8) s_adj[half][w + 8 * lane] = val;

        asm volatile("bar.sync %0, 256;" :: "r"(bar_id) : "memory");

        if (th == 0 && it + NBUF < iters) {
            uint32_t mb = mb_base + b * 8;
            asm volatile("mbarrier.arrive.expect_tx.shared::cta.b64 _, [%0], %1;"
                         :: "r"(mb), "r"(65536));
            asm volatile(
                "cp.async.bulk.shared::cta.global.mbarrier::complete_tx::bytes "
                "[%0], [%1], %2, [%3];"
                :: "r"(sA_base + b * 65536),
                   "l"(anchor + (size_t)(row + NBUF * NCTA) * AA * DD),
                   "r"(65536), "r"(mb) : "memory");
        }

        float p0, p1;
        {
            float v0 = s_adj[half][lane], v1 = s_adj[half][lane + 32];
            float sum = v0 + v1;
            float mx = fmaxf(v0, v1);
#pragma unroll
            for (int o = 16; o; o >>= 1) {
                sum += __shfl_xor_sync(0xffffffffu, sum, o);
                mx = fmaxf(mx, __shfl_xor_sync(0xffffffffu, mx, o));
            }
            if (sum != 0.0f) {
                float e0 = __expf(v0 - mx), e1 = __expf(v1 - mx);
                float es = e0 + e1;
#pragma unroll
                for (int o = 16; o; o >>= 1) es += __shfl_xor_sync(0xffffffffu, es, o);
                float inv = 1.0f / es;
                p0 = e0 * inv;
                p1 = e1 * inv;
                if (th == 0) g_S[row] = 1.0f;
            } else {
                p0 = v0;
                p1 = v1;
                if (th == 0) g_S[row] = 0.0f;
            }
        }
        float pa[8];
#pragma unroll
        for (int j = 0; j < 4; ++j)
            pa[j] = __shfl_sync(0xffffffffu, p0, w + 8 * j);
#pragma unroll
        for (int j = 4; j < 8; ++j)
            pa[j] = __shfl_sync(0xffffffffu, p1, w + 8 * j - 32);

        float4 acc0 = make_float4(0.f, 0.f, 0.f, 0.f);
        float4 acc1 = make_float4(0.f, 0.f, 0.f, 0.f);
#pragma unroll
        for (int j = 0; j < 8; ++j) {
            acc0.x = fmaf(pa[j], x0[j].x, acc0.x);
            acc0.y = fmaf(pa[j], x0[j].y, acc0.y);
            acc0.z = fmaf(pa[j], x0[j].z, acc0.z);
            acc0.w = fmaf(pa[j], x0[j].w, acc0.w);
            acc1.x = fmaf(pa[j], x1[j].x, acc1.x);
            acc1.y = fmaf(pa[j], x1[j].y, acc1.y);
            acc1.z = fmaf(pa[j], x1[j].z, acc1.z);
            acc1.w = fmaf(pa[j], x1[j].w, acc1.w);
        }
        float* myP = sP + (half * 8 + w) * DD;
        *reinterpret_cast<float4*>(myP + lane * 4) = acc0;
        *reinterpret_cast<float4*>(myP + 128 + lane * 4) = acc1;

        asm volatile("bar.sync %0, 256;" :: "r"(bar_id) : "memory");

        {
            const float* hp = sP + half * 8 * DD;
            float a = 0.f;
#pragma unroll
            for (int i = 0; i < 8; ++i) a += hp[i * DD + th];
            g_wsum[(size_t)row * DD + th] = a;
        }
    }
}

// ---------------- launch ----------------------------------------------------
extern "C" void kernel_launch(void* const* d_in, const int* in_sizes, int n_in,
                              void* d_out, int out_size) {
    const float* cc     = (const float*)d_in[0];
    const float* anchor = (const float*)d_in[1];
    const float* sims   = (const float*)d_in[2];
    const float* Wq     = (const float*)d_in[3];
    const float* bq     = (const float*)d_in[4];
    const float* Wk     = (const float*)d_in[5];
    const float* bk     = (const float*)d_in[6];
    const float* Wv     = (const float*)d_in[7];
    const float* bv     = (const float*)d_in[8];
    float* out = (float*)d_out;

    const int smem_attn = (NBUF * AA * DD + 16 * DD) * (int)sizeof(float);  // 208 KB
    cudaFuncSetAttribute(attn_v7, cudaFuncAttributeMaxDynamicSharedMemorySize,
                         smem_attn);
    cudaFuncSetAttribute(mma_gemm<0>, cudaFuncAttributeMaxDynamicSharedMemorySize,
                         MMA_SMEM);
    cudaFuncSetAttribute(mma_gemm<1>, cudaFuncAttributeMaxDynamicSharedMemorySize,
                         MMA_SMEM);

    prep_all<<<20, 256>>>(Wq, bq, Wk, bk, Wv);
    mma_gemm<0><<<dim3(32, 4), 512, MMA_SMEM>>>(cc, nullptr, nullptr);
    attn_v7<<<NCTA, 512, smem_attn>>>(anchor, sims);
    mma_gemm<1><<<dim3(32, 4), 512, MMA_SMEM>>>(nullptr, bv, out);
}

// round 17
// speedup vs baseline: 1.2603x; 1.0251x over previous
#include <cuda_runtime.h>
#include <cuda_fp16.h>
#include <math.h>
#include <stdint.h>

#define DD 256
#define AA 64
#define NROWS 4096   // B*N
#define NCTA 148     // persistent CTAs for attn
#define NBUF 3       // pipeline depth
#define KP 264       // padded row length (fp16 elems); 528 B rows
#define KPB 528
#define LO_SCALE 2048.0f
#define LO_INV 4.8828125e-4f  // 1/2048

// ---------------- scratch (device globals; no allocation allowed) ----------
__device__ float g_b2[DD];           // scale * bq @ Wk   (bias for Qk)
__device__ float g_u[DD];            // scale * Wq^T @ bk
__device__ float g_c;                // scale * bq . bk
__device__ float g_Qk[NROWS * DD];   // cc @ W2 + b2  (fp32, read by attn)
__device__ float g_qb[NROWS];        // cc_row . g_u + g_c
__device__ float g_wsum[NROWS * DD]; // sum_a p[a] * anchor[a,:]
__device__ float g_S[NROWS];         // softmax flag
// pre-split, pre-padded fp16 weight matrices (row stride KP, [n][k])
// lo parts stored scaled by 2048 to stay in normal fp16 range
__device__ __align__(16) __half g_BH0[DD * KP];  // W2^T hi
__device__ __align__(16) __half g_BL0[DD * KP];  // W2^T lo*2048
__device__ __align__(16) __half g_BH1[DD * KP];  // Wv hi
__device__ __align__(16) __half g_BL1[DD * KP];  // Wv lo*2048

// ---------------- small helpers ---------------------------------------------
__device__ __forceinline__ uint32_t smem_u32(const void* p) {
    uint32_t a;
    asm("{ .reg .u64 x; cvta.to.shared.u64 x, %1; cvt.u32.u64 %0, x; }"
        : "=r"(a) : "l"(p));
    return a;
}
__device__ __forceinline__ void hsplit(float x, __half& h, __half& l) {
    h = __float2half_rn(x);
    l = __float2half_rn((x - __half2float(h)) * LO_SCALE);
}
__device__ __forceinline__ uint32_t hpack(__half a, __half b) {
    __half2 v;
    v.x = a;
    v.y = b;
    return *reinterpret_cast<uint32_t*>(&v);
}

// ---------------- mma / ldmatrix wrappers ------------------------------------
__device__ __forceinline__ void ldsm_x4(uint32_t addr, uint32_t& r0, uint32_t& r1,
                                        uint32_t& r2, uint32_t& r3) {
    asm volatile("ldmatrix.sync.aligned.m8n8.x4.shared.b16 {%0,%1,%2,%3}, [%4];"
                 : "=r"(r0), "=r"(r1), "=r"(r2), "=r"(r3) : "r"(addr));
}
__device__ __forceinline__ void mma_fp16(float* d, uint32_t a0, uint32_t a1,
                                         uint32_t a2, uint32_t a3, uint32_t b0,
                                         uint32_t b1) {
    asm volatile(
        "mma.sync.aligned.m16n8k16.row.col.f32.f16.f16.f32 "
        "{%0,%1,%2,%3}, {%4,%5,%6,%7}, {%8,%9}, {%0,%1,%2,%3};"
        : "+f"(d[0]), "+f"(d[1]), "+f"(d[2]), "+f"(d[3])
        : "r"(a0), "r"(a1), "r"(a2), "r"(a3), "r"(b0), "r"(b1));
}

// ---------------- prep_all: weights -> split/padded; vectors ----------------
__device__ __forceinline__ void mma_tile4(const float (*As)[68], const float (*Bs)[68],
                                          int ty, int tx, float acc[4][4]) {
#pragma unroll
    for (int kk = 0; kk < 16; ++kk) {
        float4 av = *reinterpret_cast<const float4*>(&As[kk][ty * 4]);
        float4 bv = *reinterpret_cast<const float4*>(&Bs[kk][tx * 4]);
        float ar[4] = {av.x, av.y, av.z, av.w};
        float br[4] = {bv.x, bv.y, bv.z, bv.w};
#pragma unroll
        for (int i = 0; i < 4; ++i)
#pragma unroll
            for (int j = 0; j < 4; ++j)
                acc[i][j] = fmaf(ar[i], br[j], acc[i][j]);
    }
}

__global__ __launch_bounds__(256) void prep_all(const float* __restrict__ Wq,
                                                const float* __restrict__ bq,
                                                const float* __restrict__ Wk,
                                                const float* __restrict__ bk,
                                                const float* __restrict__ Wv) {
    const float scale = 0.0625f;  // 1/sqrt(256)
    const int blk = blockIdx.x;
    const int t = threadIdx.x;
    if (blk >= 18) {
        // Wv rows -> g_BH1/g_BL1 (padded layout)
        const int rbase = (blk - 18) * 128;
#pragma unroll
        for (int i = 0; i < 16; ++i) {
            int u = t + i * 256;            // 4096 units = 128 rows x 32 kg
            int r = rbase + (u >> 5), kg = u & 31;
            const float* ap = Wv + (size_t)r * DD + kg * 8;
            float4 f0 = *reinterpret_cast<const float4*>(ap);
            float4 f1 = *reinterpret_cast<const float4*>(ap + 4);
            __half h0, h1, h2, h3, h4, h5, h6, h7;
            __half l0, l1, l2, l3, l4, l5, l6, l7;
            hsplit(f0.x, h0, l0); hsplit(f0.y, h1, l1);
            hsplit(f0.z, h2, l2); hsplit(f0.w, h3, l3);
            hsplit(f1.x, h4, l4); hsplit(f1.y, h5, l5);
            hsplit(f1.z, h6, l6); hsplit(f1.w, h7, l7);
            uint4 vh = make_uint4(hpack(h0, h1), hpack(h2, h3), hpack(h4, h5),
                                  hpack(h6, h7));
            uint4 vl = make_uint4(hpack(l0, l1), hpack(l2, l3), hpack(l4, l5),
                                  hpack(l6, l7));
            *reinterpret_cast<uint4*>(&g_BH1[(size_t)r * KP + kg * 8]) = vh;
            *reinterpret_cast<uint4*>(&g_BL1[(size_t)r * KP + kg * 8]) = vl;
        }
        return;
    }
    if (blk >= 16) {
        if (blk == 16) {
            float s0 = 0.f, s1 = 0.f, s2 = 0.f, s3 = 0.f;
#pragma unroll 16
            for (int k = 0; k < DD; k += 4) {
                s0 = fmaf(Wq[(k + 0) * DD + t], bk[k + 0], s0);
                s1 = fmaf(Wq[(k + 1) * DD + t], bk[k + 1], s1);
                s2 = fmaf(Wq[(k + 2) * DD + t], bk[k + 2], s2);
                s3 = fmaf(Wq[(k + 3) * DD + t], bk[k + 3], s3);
            }
            g_u[t] = scale * ((s0 + s1) + (s2 + s3));
            if (t == 0) {
                float c0 = 0.f, c1 = 0.f;
#pragma unroll 16
                for (int k = 0; k < DD; k += 2) {
                    c0 = fmaf(bq[k], bk[k], c0);
                    c1 = fmaf(bq[k + 1], bk[k + 1], c1);
                }
                g_c = scale * (c0 + c1);
            }
        } else {
            float s0 = 0.f, s1 = 0.f, s2 = 0.f, s3 = 0.f;
#pragma unroll 16
            for (int k = 0; k < DD; k += 4) {
                s0 = fmaf(bq[k + 0], Wk[(k + 0) * DD + t], s0);
                s1 = fmaf(bq[k + 1], Wk[(k + 1) * DD + t], s1);
                s2 = fmaf(bq[k + 2], Wk[(k + 2) * DD + t], s2);
                s3 = fmaf(bq[k + 3], Wk[(k + 3) * DD + t], s3);
            }
            g_b2[t] = scale * ((s0 + s1) + (s2 + s3));
        }
        return;
    }
    // W2 tile = scale * Wq^T @ Wk; store transposed split: BT0[e][d]
    __shared__ float As[16][68];
    __shared__ float Bs[16][68];
    int tx = t % 16, ty = t / 16;
    int d0 = (blk % 4) * 64, e0 = (blk / 4) * 64;
    float acc[4][4] = {};
    for (int k0 = 0; k0 < DD; k0 += 16) {
        float4 a = *reinterpret_cast<const float4*>(Wq + (k0 + ty) * DD + d0 + tx * 4);
        float4 b = *reinterpret_cast<const float4*>(Wk + (k0 + ty) * DD + e0 + tx * 4);
        *reinterpret_cast<float4*>(&As[ty][tx * 4]) = a;
        *reinterpret_cast<float4*>(&Bs[ty][tx * 4]) = b;
        __syncthreads();
        mma_tile4(As, Bs, ty, tx, acc);
        __syncthreads();
    }
#pragma unroll
    for (int i = 0; i < 4; ++i)
#pragma unroll
        for (int j = 0; j < 4; ++j) {
            float v = scale * acc[i][j];
            __half h, l;
            hsplit(v, h, l);
            int e = e0 + tx * 4 + j, d = d0 + ty * 4 + i;
            g_BH0[(size_t)e * KP + d] = h;
            g_BL0[(size_t)e * KP + d] = l;
        }
}

// ---------------- HMMA GEMM v5: fp16 2-pass, decoupled k-split sets ---------
// C[4096,256] = A @ B^T (+bias); D = Ah*Bh + Ah*(Bl/2048)
// A rounded to fp16 once (rn, err 2^-11); B pre-split (captured to ~2^-22).
// tile M=128, N=64, K=256; 512 thr; set s stages+computes its own k-half.
#define SM_MB   0
#define SM_BIAS 16
#define SM_U    1024
#define SM_QB   2048                  // float[2][128]
#define SM_A    4096
#define SM_BH   (SM_A + 128 * KPB)    // 71680
#define SM_BL   (SM_BH + 64 * KPB)    // 105472
#define MMA_SMEM (SM_BL + 64 * KPB)   // 139264
#define SM_RED  SM_A
#define TXB     (2 * 64 * KPB)        // B hi+lo bytes

template <int BMODE>
__global__ __launch_bounds__(512) void mma_gemm(const float* __restrict__ Afp,
                                                const float* __restrict__ biasp,
                                                float* __restrict__ Cp) {
    extern __shared__ char dsm[];
    const float* A = (BMODE == 0) ? Afp : g_wsum;
    const __half* BHg = (BMODE == 0) ? g_BH0 : g_BH1;
    const __half* BLg = (BMODE == 0) ? g_BL0 : g_BL1;
    const float* bias = (BMODE == 0) ? g_b2 : biasp;
    float* C = (BMODE == 0) ? g_Qk : Cp;

    const int t = threadIdx.x;
    const int w = t >> 5, lane = t & 31;
    const int wset = w >> 3, wp = w & 7;
    const int m0 = blockIdx.x * 128, n0 = blockIdx.y * 64;
    const uint32_t sb = smem_u32(dsm);
    const bool qb_active = (BMODE == 0) && (blockIdx.y == 0);

    if (t == 0)
        asm volatile("mbarrier.init.shared::cta.b64 [%0], 1;" :: "r"(sb + SM_MB)
                     : "memory");
    __syncthreads();
    // issue B DMA first: hides under A staging
    if (t == 0) {
        asm volatile("mbarrier.arrive.expect_tx.shared::cta.b64 _, [%0], %1;"
                     :: "r"(sb + SM_MB), "r"((uint32_t)TXB) : "memory");
        asm volatile(
            "cp.async.bulk.shared::cta.global.mbarrier::complete_tx::bytes "
            "[%0], [%1], %2, [%3];"
            :: "r"(sb + SM_BH), "l"(BHg + (size_t)n0 * KP),
               "r"(64 * KPB), "r"(sb + SM_MB) : "memory");
        asm volatile(
            "cp.async.bulk.shared::cta.global.mbarrier::complete_tx::bytes "
            "[%0], [%1], %2, [%3];"
            :: "r"(sb + SM_BL), "l"(BLg + (size_t)n0 * KP),
               "r"(64 * KPB), "r"(sb + SM_MB) : "memory");
    }
    if (t < 64)
        *reinterpret_cast<float*>(dsm + SM_BIAS + t * 4) = bias[n0 + t];
    if (qb_active) {
        if (t < DD) *reinterpret_cast<float*>(dsm + SM_U + t * 4) = g_u[t];
        __syncthreads();  // s_u visible to both sets before staging dots
    }

    // ---- per-set A staging (fp16 round only): all 128 rows, own 16 kg half --
    const float* s_u = reinterpret_cast<const float*>(dsm + SM_U);
    float* s_qbp = reinterpret_cast<float*>(dsm + SM_QB);
    const int kg0 = wset * 16;
#pragma unroll
    for (int i = 0; i < 8; ++i) {
        const int rl = i * 2 + (lane >> 4);
        const int r = wp * 16 + rl;
        const int kg = kg0 + (lane & 15);
        const float* ap = A + (size_t)(m0 + r) * DD + kg * 8;
        float4 f0 = *reinterpret_cast<const float4*>(ap);
        float4 f1 = *reinterpret_cast<const float4*>(ap + 4);
        if (qb_active) {
            const float* uu = s_u + kg * 8;
            float p = f0.x * uu[0] + f0.y * uu[1] + f0.z * uu[2] + f0.w * uu[3] +
                      f1.x * uu[4] + f1.y * uu[5] + f1.z * uu[6] + f1.w * uu[7];
            p += __shfl_xor_sync(0xffffffffu, p, 8);
            p += __shfl_xor_sync(0xffffffffu, p, 4);
            p += __shfl_xor_sync(0xffffffffu, p, 2);
            p += __shfl_xor_sync(0xffffffffu, p, 1);
            if ((lane & 15) == 0) s_qbp[wset * 128 + r] = p;
        }
        uint4 vh = make_uint4(
            hpack(__float2half_rn(f0.x), __float2half_rn(f0.y)),
            hpack(__float2half_rn(f0.z), __float2half_rn(f0.w)),
            hpack(__float2half_rn(f1.x), __float2half_rn(f1.y)),
            hpack(__float2half_rn(f1.z), __float2half_rn(f1.w)));
        *reinterpret_cast<uint4*>(dsm + SM_A + r * KPB + kg * 16) = vh;
    }
    // per-set ordering: this set's A half staged (by this set's 256 threads)
    asm volatile("bar.sync %0, 256;" :: "r"(1 + wset) : "memory");
    // wait for B DMA (usually complete by now)
    asm volatile(
        "{ .reg .pred P;\n"
        "WL%=: mbarrier.try_wait.parity.acquire.cta.shared::cta.b64 P, [%0], 0;\n"
        "@!P bra WL%=; }"
        :: "r"(sb + SM_MB) : "memory");

    // ---- mainloop: set s runs k-steps j0..j0+7, 2 passes, A prefetch --------
    const uint32_t laneA = (16 * wp + (lane & 15)) * KPB + (lane >> 4) * 16;
    const uint32_t laneB =
        (((lane >> 4) * 8) + (lane & 7)) * KPB + ((lane >> 3) & 1) * 16;

    float dh[8][4], dl[8][4];
#pragma unroll
    for (int v = 0; v < 8; ++v)
#pragma unroll
        for (int i = 0; i < 4; ++i) {
            dh[v][i] = 0.f;
            dl[v][i] = 0.f;
        }

    const int j0 = wset * 8;
    uint32_t a0, a1, a2, a3;
    ldsm_x4(sb + SM_A + laneA + (uint32_t)j0 * 32, a0, a1, a2, a3);
#pragma unroll
    for (int jj = 0; jj < 8; ++jj) {
        const uint32_t koff = (uint32_t)(j0 + jj) * 32;
        uint32_t n0r, n1r, n2r, n3r;
        if (jj < 7)
            ldsm_x4(sb + SM_A + laneA + koff + 32, n0r, n1r, n2r, n3r);
#pragma unroll
        for (int p = 0; p < 4; ++p) {
            const uint32_t prow = p * 16 * KPB;
            uint32_t bh0, bh1, bh2, bh3, bl0, bl1, bl2, bl3;
            ldsm_x4(sb + SM_BH + prow + laneB + koff, bh0, bh1, bh2, bh3);
            ldsm_x4(sb + SM_BL + prow + laneB + koff, bl0, bl1, bl2, bl3);
            mma_fp16(dh[2 * p], a0, a1, a2, a3, bh0, bh1);
            mma_fp16(dh[2 * p + 1], a0, a1, a2, a3, bh2, bh3);
            mma_fp16(dl[2 * p], a0, a1, a2, a3, bl0, bl1);
            mma_fp16(dl[2 * p + 1], a0, a1, a2, a3, bl2, bl3);
        }
        if (jj < 7) {
            a0 = n0r; a1 = n1r; a2 = n2r; a3 = n3r;
        }
    }
    // combine hi + scaled lo
    float d[8][4];
#pragma unroll
    for (int v = 0; v < 8; ++v)
#pragma unroll
        for (int i = 0; i < 4; ++i) d[v][i] = fmaf(dl[v][i], LO_INV, dh[v][i]);

    __syncthreads();  // both sets done; A region dead -> reduction buffer

    if (qb_active && t < 128)
        g_qb[m0 + t] = s_qbp[t] + s_qbp[128 + t] + g_c;

    if (wset == 1) {
        float4* red = reinterpret_cast<float4*>(dsm + SM_RED) +
                      (size_t)(wp * 32 + lane) * 8;
#pragma unroll
        for (int v = 0; v < 8; ++v)
            red[v] = make_float4(d[v][0], d[v][1], d[v][2], d[v][3]);
    }
    __syncthreads();

    if (wset == 0) {
        const float4* red = reinterpret_cast<const float4*>(dsm + SM_RED) +
                            (size_t)(wp * 32 + lane) * 8;
        const float* s_bias = reinterpret_cast<const float*>(dsm + SM_BIAS);
        const int gm = m0 + 16 * wp + (lane >> 2);
        const int cn = 2 * (lane & 3);
        float sv0 = 1.f, sv1 = 1.f;
        if (BMODE == 1) {
            sv0 = g_S[gm];
            sv1 = g_S[gm + 8];
        }
#pragma unroll
        for (int v = 0; v < 8; ++v) {
            float4 r = red[v];
            const int n = 8 * v + cn;
            const float b0 = s_bias[n], b1 = s_bias[n + 1];
            float2 o0 = make_float2(d[v][0] + r.x + b0 * sv0,
                                    d[v][1] + r.y + b1 * sv0);
            float2 o1 = make_float2(d[v][2] + r.z + b0 * sv1,
                                    d[v][3] + r.w + b1 * sv1);
            *reinterpret_cast<float2*>(C + (size_t)gm * DD + n0 + n) = o0;
            *reinterpret_cast<float2*>(C + (size_t)(gm + 8) * DD + n0 + n) = o1;
        }
    }
}

// ---------------- attn v7: two independent 256-thread halves per CTA --------
__global__ __launch_bounds__(512) void attn_v7(const float* __restrict__ anchor,
                                               const float* __restrict__ sims) {
    extern __shared__ float sm[];
    float* sP = sm + NBUF * AA * DD;  // [2 halves][8 warps][256]
    __shared__ float s_adj[2][AA];
    __shared__ __align__(8) unsigned long long mbar[NBUF];

    const int t = threadIdx.x;
    const int half = t >> 8;
    const int th = t & 255;
    const int w = th >> 5;
    const int lane = t & 31;
    const int cta = blockIdx.x;
    const int iters = (NROWS - cta + NCTA - 1) / NCTA;

    uint32_t mb_base, sA_base;
    asm("{ .reg .u64 x; cvta.to.shared.u64 x, %1; cvt.u32.u64 %0, x; }"
        : "=r"(mb_base) : "l"(mbar));
    asm("{ .reg .u64 x; cvta.to.shared.u64 x, %1; cvt.u32.u64 %0, x; }"
        : "=r"(sA_base) : "l"(sm));

    if (t == 0) {
#pragma unroll
        for (int j = 0; j < NBUF; ++j)
            asm volatile("mbarrier.init.shared::cta.b64 [%0], 1;"
                         :: "r"(mb_base + j * 8));
    }
    __syncthreads();
    if (t == 0) {
#pragma unroll
        for (int j = 0; j < NBUF; ++j)
            if (j < iters) {
                uint32_t mb = mb_base + j * 8;
                asm volatile("mbarrier.arrive.expect_tx.shared::cta.b64 _, [%0], %1;"
                             :: "r"(mb), "r"(65536));
                asm volatile(
                    "cp.async.bulk.shared::cta.global.mbarrier::complete_tx::bytes "
                    "[%0], [%1], %2, [%3];"
                    :: "r"(sA_base + j * 65536),
                       "l"(anchor + (size_t)(cta + j * NCTA) * AA * DD),
                       "r"(65536), "r"(mb) : "memory");
            }
    }
    __syncthreads();

    const int bar_id = 1 + half;

    for (int it = half; it < iters; it += 2) {
        const int row = cta + it * NCTA;
        const int b = it % NBUF;
        const float* sA = sm + b * AA * DD;

        const float4* qg = reinterpret_cast<const float4*>(g_Qk + (size_t)row * DD);
        float4 q0 = qg[lane], q1 = qg[lane + 32];
        float qb = g_qb[row];
        float simv = (lane < 8) ? sims[row * AA + w + 8 * lane] : 0.f;

        {
            uint32_t mb = mb_base + b * 8;
            int par = (it / NBUF) & 1;
            asm volatile(
                "{ .reg .pred P;\n"
                "WL%=: mbarrier.try_wait.parity.acquire.cta.shared::cta.b64 P, [%0], %1;\n"
                "@!P bra WL%=; }"
                :: "r"(mb), "r"(par) : "memory");
        }

        float4 x0[8], x1[8];
        float val = 0.f;
#pragma unroll
        for (int j = 0; j < 8; ++j) {
            const int a = w + 8 * j;
            const float4* a4 = reinterpret_cast<const float4*>(sA + a * DD);
            x0[j] = a4[lane];
            x1[j] = a4[lane + 32];
            float s = q0.x * x0[j].x + q0.y * x0[j].y + q0.z * x0[j].z +
                      q0.w * x0[j].w + q1.x * x1[j].x + q1.y * x1[j].y +
                      q1.z * x1[j].z + q1.w * x1[j].w;
#pragma unroll
            for (int o = 16; o; o >>= 1) s += __shfl_xor_sync(0xffffffffu, s, o);
            if (lane == j) val = s + qb + simv;
        }
        if (lane < 8) s_adj[half][w + 8 * lane] = val;

        asm volatile("bar.sync %0, 256;" :: "r"(bar_id) : "memory");

        if (th == 0 && it + NBUF < iters) {
            uint32_t mb = mb_base + b * 8;
            asm volatile("mbarrier.arrive.expect_tx.shared::cta.b64 _, [%0], %1;"
                         :: "r"(mb), "r"(65536));
            asm volatile(
                "cp.async.bulk.shared::cta.global.mbarrier::complete_tx::bytes "
                "[%0], [%1], %2, [%3];"
                :: "r"(sA_base + b * 65536),
                   "l"(anchor + (size_t)(row + NBUF * NCTA) * AA * DD),
                   "r"(65536), "r"(mb) : "memory");
        }

        float p0, p1;
        {
            float v0 = s_adj[half][lane], v1 = s_adj[half][lane + 32];
            float sum = v0 + v1;
            float mx = fmaxf(v0, v1);
#pragma unroll
            for (int o = 16; o; o >>= 1) {
                sum += __shfl_xor_sync(0xffffffffu, sum, o);
                mx = fmaxf(mx, __shfl_xor_sync(0xffffffffu, mx, o));
            }
            if (sum != 0.0f) {
                float e0 = __expf(v0 - mx), e1 = __expf(v1 - mx);
                float es = e0 + e1;
#pragma unroll
                for (int o = 16; o; o >>= 1) es += __shfl_xor_sync(0xffffffffu, es, o);
                float inv = 1.0f / es;
                p0 = e0 * inv;
                p1 = e1 * inv;
                if (th == 0) g_S[row] = 1.0f;
            } else {
                p0 = v0;
                p1 = v1;
                if (th == 0) g_S[row] = 0.0f;
            }
        }
        float pa[8];
#pragma unroll
        for (int j = 0; j < 4; ++j)
            pa[j] = __shfl_sync(0xffffffffu, p0, w + 8 * j);
#pragma unroll
        for (int j = 4; j < 8; ++j)
            pa[j] = __shfl_sync(0xffffffffu, p1, w + 8 * j - 32);

        float4 acc0 = make_float4(0.f, 0.f, 0.f, 0.f);
        float4 acc1 = make_float4(0.f, 0.f, 0.f, 0.f);
#pragma unroll
        for (int j = 0; j < 8; ++j) {
            acc0.x = fmaf(pa[j], x0[j].x, acc0.x);
            acc0.y = fmaf(pa[j], x0[j].y, acc0.y);
            acc0.z = fmaf(pa[j], x0[j].z, acc0.z);
            acc0.w = fmaf(pa[j], x0[j].w, acc0.w);
            acc1.x = fmaf(pa[j], x1[j].x, acc1.x);
            acc1.y = fmaf(pa[j], x1[j].y, acc1.y);
            acc1.z = fmaf(pa[j], x1[j].z, acc1.z);
            acc1.w = fmaf(pa[j], x1[j].w, acc1.w);
        }
        float* myP = sP + (half * 8 + w) * DD;
        *reinterpret_cast<float4*>(myP + lane * 4) = acc0;
        *reinterpret_cast<float4*>(myP + 128 + lane * 4) = acc1;

        asm volatile("bar.sync %0, 256;" :: "r"(bar_id) : "memory");

        {
            const float* hp = sP + half * 8 * DD;
            float a = 0.f;
#pragma unroll
            for (int i = 0; i < 8; ++i) a += hp[i * DD + th];
            g_wsum[(size_t)row * DD + th] = a;
        }
    }
}

// ---------------- launch ----------------------------------------------------
extern "C" void kernel_launch(void* const* d_in, const int* in_sizes, int n_in,
                              void* d_out, int out_size) {
    const float* cc     = (const float*)d_in[0];
    const float* anchor = (const float*)d_in[1];
    const float* sims   = (const float*)d_in[2];
    const float* Wq     = (const float*)d_in[3];
    const float* bq     = (const float*)d_in[4];
    const float* Wk     = (const float*)d_in[5];
    const float* bk     = (const float*)d_in[6];
    const float* Wv     = (const float*)d_in[7];
    const float* bv     = (const float*)d_in[8];
    float* out = (float*)d_out;

    const int smem_attn = (NBUF * AA * DD + 16 * DD) * (int)sizeof(float);  // 208 KB
    cudaFuncSetAttribute(attn_v7, cudaFuncAttributeMaxDynamicSharedMemorySize,
                         smem_attn);
    cudaFuncSetAttribute(mma_gemm<0>, cudaFuncAttributeMaxDynamicSharedMemorySize,
                         MMA_SMEM);
    cudaFuncSetAttribute(mma_gemm<1>, cudaFuncAttributeMaxDynamicSharedMemorySize,
                         MMA_SMEM);

    prep_all<<<20, 256>>>(Wq, bq, Wk, bk, Wv);
    mma_gemm<0><<<dim3(32, 4), 512, MMA_SMEM>>>(cc, nullptr, nullptr);
    attn_v7<<<NCTA, 512, smem_attn>>>(anchor, sims);
    mma_gemm<1><<<dim3(32, 4), 512, MMA_SMEM>>>(nullptr, bv, out);
}